// round 10
// baseline (speedup 1.0000x reference)
#include <cuda_runtime.h>
#include <cuda_bf16.h>
#include <cstdint>

// ---------------------------------------------------------------------------
// BigramTransformer forward — HMMA bf16-split GEMMs + fused-LN epilogues.
// B=2048 T=64 D=128 H=4 HD=32 L=6 V=256 DFF=512
// ---------------------------------------------------------------------------

#define Bc   2048
#define Tc   64
#define Dc   128
#define Hc   4
#define HDc  32
#define Lc   6
#define Vc   256
#define DFFc 512
#define NTOK (Bc * Tc)          /* 131072 */
#define QKVC (3 * Dc)           /* 384    */

// ------------------------- scratch (device globals) ------------------------
__device__ float g_x  [(size_t)NTOK * Dc];
__device__ float g_qkv[(size_t)NTOK * QKVC];
__device__ __nv_bfloat16 g_hh[(size_t)NTOK * Dc],   g_hl[(size_t)NTOK * Dc];
__device__ __nv_bfloat16 g_ah[(size_t)NTOK * Dc],   g_al[(size_t)NTOK * Dc];
__device__ __nv_bfloat16 g_mh[(size_t)NTOK * DFFc], g_ml[(size_t)NTOK * DFFc];
// transposed bf16 weights [N,K] hi/lo
__device__ __nv_bfloat16 g_wqkv_h[Lc * QKVC * Dc],  g_wqkv_l[Lc * QKVC * Dc];
__device__ __nv_bfloat16 g_wo_h  [Lc * Dc * Dc],    g_wo_l  [Lc * Dc * Dc];
__device__ __nv_bfloat16 g_w1_h  [Lc * DFFc * Dc],  g_w1_l  [Lc * DFFc * Dc];
__device__ __nv_bfloat16 g_w2_h  [Lc * Dc * DFFc],  g_w2_l  [Lc * Dc * DFFc];
__device__ __nv_bfloat16 g_whd_h [Vc * Dc],         g_whd_l [Vc * Dc];

// ------------------------- helpers ------------------------------------------
__device__ __forceinline__ uint32_t smem_u32(const void* p) {
    uint32_t a;
    asm("{ .reg .u64 t; cvta.to.shared.u64 t, %1; cvt.u32.u64 %0, t; }"
        : "=r"(a) : "l"(p));
    return a;
}
__device__ __forceinline__ void hilo_store2(float v0, float v1,
                                            __nv_bfloat16* ph, __nv_bfloat16* pl) {
    __nv_bfloat16 h0 = __float2bfloat16(v0), h1 = __float2bfloat16(v1);
    __nv_bfloat162 hh; hh.x = h0; hh.y = h1;
    __nv_bfloat162 ll;
    ll.x = __float2bfloat16(v0 - __bfloat162float(h0));
    ll.y = __float2bfloat16(v1 - __bfloat162float(h1));
    *(__nv_bfloat162*)ph = hh;
    *(__nv_bfloat162*)pl = ll;
}

#define LDMX4(r0, r1, r2, r3, a)                                            \
    asm volatile("ldmatrix.sync.aligned.m8n8.x4.shared.b16 {%0,%1,%2,%3}, [%4];" \
                 : "=r"(r0), "=r"(r1), "=r"(r2), "=r"(r3) : "r"(a))

#define MMA(d, a, b0v, b1v)                                                 \
    asm volatile("mma.sync.aligned.m16n8k16.row.col.f32.bf16.bf16.f32 "     \
                 "{%0,%1,%2,%3}, {%4,%5,%6,%7}, {%8,%9}, {%0,%1,%2,%3};"    \
                 : "+f"((d)[0]), "+f"((d)[1]), "+f"((d)[2]), "+f"((d)[3])   \
                 : "r"((a)[0]), "r"((a)[1]), "r"((a)[2]), "r"((a)[3]),      \
                   "r"(b0v), "r"(b1v))

#define CP_ASYNC16(dst, src)                                                \
    asm volatile("cp.async.cg.shared.global [%0], [%1], 16;"                \
                 :: "r"(dst), "l"(src))
#define CP_COMMIT() asm volatile("cp.async.commit_group;" ::: "memory")
#define CP_WAIT0()  asm volatile("cp.async.wait_group 0;" ::: "memory")

// ------------------------- weight conversion --------------------------------
__global__ void convw_kernel(const float* __restrict__ W,
                             __nv_bfloat16* __restrict__ oh,
                             __nv_bfloat16* __restrict__ ol, int K, int N)
{
    const size_t base = (size_t)blockIdx.y * K * N;
    int i = blockIdx.x * 256 + threadIdx.x;
    if (i >= K * N) return;
    int k = i / N, n = i % N;
    float v = W[base + i];
    __nv_bfloat16 h = __float2bfloat16(v);
    oh[base + (size_t)n * K + k] = h;
    ol[base + (size_t)n * K + k] = __float2bfloat16(v - __bfloat162float(h));
}

__global__ void convqkv_kernel(const float* __restrict__ Wq,
                               const float* __restrict__ Wk,
                               const float* __restrict__ Wv,
                               __nv_bfloat16* __restrict__ oh,
                               __nv_bfloat16* __restrict__ ol)
{
    int i = blockIdx.x * 256 + threadIdx.x;
    const int total = Lc * Hc * Dc * HDc;
    if (i >= total) return;
    int e = i % HDc;
    int d = (i / HDc) % Dc;
    int h = (i / (HDc * Dc)) % Hc;
    int l = i / (HDc * Dc * Hc);
    int src = ((l * Hc + h) * Dc + d) * HDc + e;
    const float vq = Wq[src], vk = Wk[src], vv = Wv[src];
    const int col = h * HDc + e;
    size_t dq = ((size_t)l * QKVC + col) * Dc + d;
    size_t dk = ((size_t)l * QKVC + Dc + col) * Dc + d;
    size_t dv = ((size_t)l * QKVC + 2 * Dc + col) * Dc + d;
    __nv_bfloat16 hq = __float2bfloat16(vq);
    __nv_bfloat16 hk = __float2bfloat16(vk);
    __nv_bfloat16 hv = __float2bfloat16(vv);
    oh[dq] = hq; ol[dq] = __float2bfloat16(vq - __bfloat162float(hq));
    oh[dk] = hk; ol[dk] = __float2bfloat16(vk - __bfloat162float(hk));
    oh[dv] = hv; ol[dv] = __float2bfloat16(vv - __bfloat162float(hv));
}

// ------------------------- embedding + first LN (warp / token) --------------
__global__ __launch_bounds__(256) void embed_ln_kernel(
    const int* __restrict__ idx,
    const float* __restrict__ tok, const float* __restrict__ pos,
    float* __restrict__ xout,
    __nv_bfloat16* __restrict__ oh, __nv_bfloat16* __restrict__ ol,
    const float* __restrict__ gam, const float* __restrict__ bet)
{
    const int warp = threadIdx.x >> 5;
    const int lane = threadIdx.x & 31;
    const size_t n = (size_t)blockIdx.x * 8 + warp;
    const int t = (int)(n & (Tc - 1));
    const int v = idx[n];

    const float4 tv = ((const float4*)(tok + (size_t)v * Dc))[lane];
    const float4 pv = ((const float4*)(pos + (size_t)t * Dc))[lane];
    float4 x = make_float4(tv.x + pv.x, tv.y + pv.y, tv.z + pv.z, tv.w + pv.w);
    ((float4*)(xout + n * Dc))[lane] = x;

    float s = x.x + x.y + x.z + x.w;
    #pragma unroll
    for (int o = 16; o > 0; o >>= 1) s += __shfl_xor_sync(0xffffffffu, s, o);
    const float mean = s * (1.0f / Dc);

    float4 c = make_float4(x.x - mean, x.y - mean, x.z - mean, x.w - mean);
    float q = c.x * c.x + c.y * c.y + c.z * c.z + c.w * c.w;
    #pragma unroll
    for (int o = 16; o > 0; o >>= 1) q += __shfl_xor_sync(0xffffffffu, q, o);
    const float r = rsqrtf(q * (1.0f / Dc) + 1e-5f);

    const float4 g = ((const float4*)gam)[lane];
    const float4 b = ((const float4*)bet)[lane];
    hilo_store2(c.x * r * g.x + b.x, c.y * r * g.y + b.y,
                oh + n * Dc + lane * 4,     ol + n * Dc + lane * 4);
    hilo_store2(c.z * r * g.z + b.z, c.w * r * g.w + b.w,
                oh + n * Dc + lane * 4 + 2, ol + n * Dc + lane * 4 + 2);
}

// ------------------------- HMMA GEMM (+ optional fused LN) ------------------
// C[M,N] = Ah@Bh^T + Ah@Bl^T + Al@Bh^T (+bias)(relu)(+res)
// If lnG != null (requires N==128, gridDim.x==1):
//   x_new = C written to outf; LN(x_new) with (lnG,lnB) written hi/lo to outh/outl.
// Else: if outh -> hi/lo output; else float output to outf.
#define TROWB 272
#define TILEB (128 * TROWB)
#define HGEMM_SMEM (4 * TILEB)

__global__ __launch_bounds__(256, 1) void hgemm_kernel(
    const __nv_bfloat16* __restrict__ Ah, const __nv_bfloat16* __restrict__ Al,
    const __nv_bfloat16* __restrict__ Bh, const __nv_bfloat16* __restrict__ Bl,
    const float* __restrict__ bias, const float* __restrict__ res,
    float* __restrict__ outf,
    __nv_bfloat16* __restrict__ outh, __nv_bfloat16* __restrict__ outl,
    const float* __restrict__ lnG, const float* __restrict__ lnB,
    int M, int N, int K, int relu)
{
    extern __shared__ char smem[];
    const uint32_t sb = smem_u32(smem);

    const int tid = threadIdx.x;
    const int w   = tid >> 5;
    const int l   = tid & 31;
    const int wm  = w & 1;
    const int wn  = w >> 1;
    const int m0  = blockIdx.y * 128;
    const int n0  = blockIdx.x * 128;

    const int g    = l >> 3;
    const int idx  = l & 7;
    const int lrow = (g & 1) * 8 + idx;
    const int g2   = (g >> 1) * 16;

    const uint32_t AHo = sb;
    const uint32_t ALo = sb + TILEB;
    const uint32_t BHo = sb + 2 * TILEB;
    const uint32_t BLo = sb + 3 * TILEB;
    const uint32_t arow = (uint32_t)(wm * 64 + lrow) * TROWB + g2;
    const uint32_t brow = (uint32_t)(wn * 32 + lrow) * TROWB + g2;

    const __nv_bfloat16* gsrc[4] = {
        Ah + (size_t)m0 * K, Al + (size_t)m0 * K,
        Bh + (size_t)n0 * K, Bl + (size_t)n0 * K };

    float acc[4][4][4] = {};

    const int nstep = K >> 7;
    for (int c = 0; c < nstep; c++) {
        if (c) __syncthreads();
        const int ck = c << 7;
        #pragma unroll
        for (int t = 0; t < 4; t++) {
            const __nv_bfloat16* src = gsrc[t];
            const uint32_t dst = sb + t * TILEB;
            #pragma unroll
            for (int i = tid; i < 2048; i += 256) {
                const int r  = i >> 4;
                const int c8 = i & 15;
                CP_ASYNC16(dst + r * TROWB + c8 * 16,
                           src + (size_t)r * K + ck + c8 * 8);
            }
        }
        CP_COMMIT();
        CP_WAIT0();
        __syncthreads();

        #pragma unroll
        for (int ks = 0; ks < 8; ks++) {
            const uint32_t kb = ks * 32;
            uint32_t ah_[4][4], al_[4][4], bh_[2][4], bl_[2][4];
            #pragma unroll
            for (int mt = 0; mt < 4; mt++) {
                const uint32_t ao = arow + mt * (16 * TROWB) + kb;
                LDMX4(ah_[mt][0], ah_[mt][1], ah_[mt][2], ah_[mt][3], AHo + ao);
                LDMX4(al_[mt][0], al_[mt][1], al_[mt][2], al_[mt][3], ALo + ao);
            }
            #pragma unroll
            for (int p = 0; p < 2; p++) {
                const uint32_t bo = brow + p * (16 * TROWB) + kb;
                LDMX4(bh_[p][0], bh_[p][1], bh_[p][2], bh_[p][3], BHo + bo);
                LDMX4(bl_[p][0], bl_[p][1], bl_[p][2], bl_[p][3], BLo + bo);
            }
            #pragma unroll
            for (int mt = 0; mt < 4; mt++) {
                #pragma unroll
                for (int nt = 0; nt < 4; nt++) {
                    const int p = nt >> 1, q = nt & 1;
                    const uint32_t b0h = bh_[p][q], b1h = bh_[p][q + 2];
                    const uint32_t b0l = bl_[p][q], b1l = bl_[p][q + 2];
                    MMA(acc[mt][nt], ah_[mt], b0h, b1h);
                    MMA(acc[mt][nt], ah_[mt], b0l, b1l);
                    MMA(acc[mt][nt], al_[mt], b0h, b1h);
                }
            }
        }
    }

    const int gr = l >> 2;
    const int gc = (l & 3) * 2;

    if (lnG) {
        // ---- fused epilogue: residual add + LN over the 128-wide row ----
        __syncthreads();                         // tiles dead; reuse smem
        float* sums  = (float*)smem;             // [128][4]
        float* sumsq = (float*)smem + 512;       // [128][4]

        #pragma unroll
        for (int mt = 0; mt < 4; mt++) {
            #pragma unroll
            for (int h = 0; h < 2; h++) {
                const int r64 = wm * 64 + mt * 16 + gr + h * 8;
                const size_t row = (size_t)m0 + r64;
                float s = 0.f, q = 0.f;
                #pragma unroll
                for (int nt = 0; nt < 4; nt++) {
                    const int n = wn * 32 + nt * 8 + gc;
                    float v0 = acc[mt][nt][h * 2];
                    float v1 = acc[mt][nt][h * 2 + 1];
                    const float2 bb = *(const float2*)(bias + n);
                    v0 += bb.x; v1 += bb.y;
                    const float2 rr = *(const float2*)(res + row * Dc + n);
                    v0 += rr.x; v1 += rr.y;
                    acc[mt][nt][h * 2]     = v0;
                    acc[mt][nt][h * 2 + 1] = v1;
                    *(float2*)(outf + row * Dc + n) = make_float2(v0, v1);
                    s += v0 + v1;
                    q += v0 * v0 + v1 * v1;
                }
                s += __shfl_xor_sync(0xffffffffu, s, 1);
                s += __shfl_xor_sync(0xffffffffu, s, 2);
                q += __shfl_xor_sync(0xffffffffu, q, 1);
                q += __shfl_xor_sync(0xffffffffu, q, 2);
                if ((l & 3) == 0) {
                    sums [r64 * 4 + wn] = s;
                    sumsq[r64 * 4 + wn] = q;
                }
            }
        }
        __syncthreads();
        #pragma unroll
        for (int mt = 0; mt < 4; mt++) {
            #pragma unroll
            for (int h = 0; h < 2; h++) {
                const int r64 = wm * 64 + mt * 16 + gr + h * 8;
                const size_t row = (size_t)m0 + r64;
                float S = sums[r64 * 4] + sums[r64 * 4 + 1]
                        + sums[r64 * 4 + 2] + sums[r64 * 4 + 3];
                float Q = sumsq[r64 * 4] + sumsq[r64 * 4 + 1]
                        + sumsq[r64 * 4 + 2] + sumsq[r64 * 4 + 3];
                const float mean = S * (1.0f / Dc);
                const float var  = Q * (1.0f / Dc) - mean * mean;
                const float rst  = rsqrtf(var + 1e-5f);
                #pragma unroll
                for (int nt = 0; nt < 4; nt++) {
                    const int n = wn * 32 + nt * 8 + gc;
                    const float2 gg = *(const float2*)(lnG + n);
                    const float2 bb = *(const float2*)(lnB + n);
                    const float v0 = acc[mt][nt][h * 2];
                    const float v1 = acc[mt][nt][h * 2 + 1];
                    hilo_store2((v0 - mean) * rst * gg.x + bb.x,
                                (v1 - mean) * rst * gg.y + bb.y,
                                outh + row * Dc + n, outl + row * Dc + n);
                }
            }
        }
        return;
    }

    // ---- plain epilogue ----
    #pragma unroll
    for (int mt = 0; mt < 4; mt++) {
        #pragma unroll
        for (int h = 0; h < 2; h++) {
            const size_t row = (size_t)m0 + wm * 64 + mt * 16 + gr + h * 8;
            #pragma unroll
            for (int nt = 0; nt < 4; nt++) {
                const int n = n0 + wn * 32 + nt * 8 + gc;
                float v0 = acc[mt][nt][h * 2];
                float v1 = acc[mt][nt][h * 2 + 1];
                if (bias) {
                    const float2 bb = *(const float2*)(bias + n);
                    v0 += bb.x; v1 += bb.y;
                }
                if (relu) { v0 = fmaxf(v0, 0.f); v1 = fmaxf(v1, 0.f); }
                if (outh) {
                    hilo_store2(v0, v1, outh + row * N + n, outl + row * N + n);
                } else {
                    *(float2*)(outf + row * N + n) = make_float2(v0, v1);
                }
            }
        }
    }
}

// ------------------------- attention: 4 (b,h) pairs per block ---------------
#define ATTN_SMEM (4 * 3 * Tc * (HDc / 4) * 16)
__global__ __launch_bounds__(256) void attn_kernel(const float* __restrict__ qkv,
                                                   __nv_bfloat16* __restrict__ oh,
                                                   __nv_bfloat16* __restrict__ ol)
{
    extern __shared__ float4 sm4[];
    const int sub = threadIdx.x >> 6;          // 0..3
    const int tid = threadIdx.x & 63;          // row t
    const int bh  = blockIdx.x * 4 + sub;
    const int b   = bh >> 2;
    const int h   = bh & 3;

    float4* qsm = sm4 + (size_t)sub * 3 * Tc * 8;
    float4* ksm = qsm + Tc * 8;
    float4* vsm = ksm + Tc * 8;

    const float* row = qkv + ((size_t)(b * Tc + tid)) * QKVC + h * HDc;
    #pragma unroll
    for (int j = 0; j < 8; j++) {
        qsm[tid * 8 + j] = *(const float4*)(row + 4 * j);
        ksm[tid * 8 + j] = *(const float4*)(row + Dc + 4 * j);
        vsm[tid * 8 + j] = *(const float4*)(row + 2 * Dc + 4 * j);
    }
    __syncthreads();

    const int t = tid;
    float q[HDc];
    #pragma unroll
    for (int j = 0; j < 8; j++) {
        float4 f = qsm[t * 8 + j];
        q[4 * j] = f.x; q[4 * j + 1] = f.y; q[4 * j + 2] = f.z; q[4 * j + 3] = f.w;
    }

    const float scale = 0.17677669529663687f;
    float sc[Tc];
    float mx = -1e30f;
    #pragma unroll
    for (int s = 0; s < Tc; s++) {
        float d = 0.f;
        #pragma unroll
        for (int j = 0; j < 8; j++) {
            float4 f = ksm[s * 8 + j];
            d = fmaf(q[4 * j],     f.x, d);
            d = fmaf(q[4 * j + 1], f.y, d);
            d = fmaf(q[4 * j + 2], f.z, d);
            d = fmaf(q[4 * j + 3], f.w, d);
        }
        d *= scale;
        sc[s] = d;
        if (s <= t) mx = fmaxf(mx, d);
    }

    float sum = 0.f;
    #pragma unroll
    for (int s = 0; s < Tc; s++) {
        float w = (s <= t) ? __expf(sc[s] - mx) : 0.f;
        sc[s] = w;
        sum += w;
    }
    const float inv = 1.f / sum;

    float4 acc[8] = {};
    #pragma unroll
    for (int s = 0; s < Tc; s++) {
        float w = sc[s];
        #pragma unroll
        for (int j = 0; j < 8; j++) {
            float4 f = vsm[s * 8 + j];
            acc[j].x = fmaf(w, f.x, acc[j].x);
            acc[j].y = fmaf(w, f.y, acc[j].y);
            acc[j].z = fmaf(w, f.z, acc[j].z);
            acc[j].w = fmaf(w, f.w, acc[j].w);
        }
    }

    const size_t base = ((size_t)(b * Tc + t)) * Dc + h * HDc;
    #pragma unroll
    for (int j = 0; j < 8; j++) {
        float4 o = acc[j];
        o.x *= inv; o.y *= inv; o.z *= inv; o.w *= inv;
        hilo_store2(o.x, o.y, oh + base + 4 * j,     ol + base + 4 * j);
        hilo_store2(o.z, o.w, oh + base + 4 * j + 2, ol + base + 4 * j + 2);
    }
}

// ------------------------- launcher -----------------------------------------
extern "C" void kernel_launch(void* const* d_in, const int* in_sizes, int n_in,
                              void* d_out, int out_size)
{
    (void)in_sizes; (void)n_in; (void)out_size;
    const int*   idx  = (const int*)  d_in[0];
    const float* tok  = (const float*)d_in[1];
    const float* pos  = (const float*)d_in[2];
    const float* Wq   = (const float*)d_in[3];
    const float* Wk   = (const float*)d_in[4];
    const float* Wv   = (const float*)d_in[5];
    const float* Wo   = (const float*)d_in[6];
    const float* bo   = (const float*)d_in[7];
    const float* ln1g = (const float*)d_in[8];
    const float* ln1b = (const float*)d_in[9];
    const float* W1   = (const float*)d_in[10];
    const float* b1   = (const float*)d_in[11];
    const float* W2   = (const float*)d_in[12];
    const float* b2   = (const float*)d_in[13];
    const float* ln2g = (const float*)d_in[14];
    const float* ln2b = (const float*)d_in[15];
    const float* lnfg = (const float*)d_in[16];
    const float* lnfb = (const float*)d_in[17];
    const float* Wh   = (const float*)d_in[18];
    const float* bhd  = (const float*)d_in[19];
    float* out = (float*)d_out;

    float *x, *qkv;
    __nv_bfloat16 *hh, *hl, *ah, *al, *mh, *ml;
    __nv_bfloat16 *wqh, *wql, *woh, *wol, *w1h, *w1l, *w2h, *w2l, *whh, *whl;
    cudaGetSymbolAddress((void**)&x,   g_x);
    cudaGetSymbolAddress((void**)&qkv, g_qkv);
    cudaGetSymbolAddress((void**)&hh,  g_hh);  cudaGetSymbolAddress((void**)&hl, g_hl);
    cudaGetSymbolAddress((void**)&ah,  g_ah);  cudaGetSymbolAddress((void**)&al, g_al);
    cudaGetSymbolAddress((void**)&mh,  g_mh);  cudaGetSymbolAddress((void**)&ml, g_ml);
    cudaGetSymbolAddress((void**)&wqh, g_wqkv_h); cudaGetSymbolAddress((void**)&wql, g_wqkv_l);
    cudaGetSymbolAddress((void**)&woh, g_wo_h);   cudaGetSymbolAddress((void**)&wol, g_wo_l);
    cudaGetSymbolAddress((void**)&w1h, g_w1_h);   cudaGetSymbolAddress((void**)&w1l, g_w1_l);
    cudaGetSymbolAddress((void**)&w2h, g_w2_h);   cudaGetSymbolAddress((void**)&w2l, g_w2_l);
    cudaGetSymbolAddress((void**)&whh, g_whd_h);  cudaGetSymbolAddress((void**)&whl, g_whd_l);

    cudaFuncSetAttribute(hgemm_kernel,
                         cudaFuncAttributeMaxDynamicSharedMemorySize, HGEMM_SMEM);
    cudaFuncSetAttribute(attn_kernel,
                         cudaFuncAttributeMaxDynamicSharedMemorySize, ATTN_SMEM);

    // weight conversion
    convqkv_kernel<<<(Lc * Hc * Dc * HDc + 255) / 256, 256>>>(Wq, Wk, Wv, wqh, wql);
    convw_kernel<<<dim3((Dc * Dc + 255) / 256, Lc), 256>>>(Wo, woh, wol, Dc, Dc);
    convw_kernel<<<dim3((Dc * DFFc + 255) / 256, Lc), 256>>>(W1, w1h, w1l, Dc, DFFc);
    convw_kernel<<<dim3((DFFc * Dc + 255) / 256, Lc), 256>>>(W2, w2h, w2l, DFFc, Dc);
    convw_kernel<<<dim3((Dc * Vc + 255) / 256, 1), 256>>>(Wh, whh, whl, Dc, Vc);

    // embed + ln1 of layer 0
    embed_ln_kernel<<<NTOK / 8, 256>>>(idx, tok, pos, x, hh, hl, ln1g, ln1b);

    const int MT = NTOK / 128;
    const dim3 gQKV(QKVC / 128, MT);
    const dim3 gD  (1,          MT);
    const dim3 gFF (DFFc / 128, MT);
    const dim3 gV  (Vc   / 128, MT);

    for (int l = 0; l < Lc; l++) {
        // QKV projection (reads hh/hl from previous fused LN)
        hgemm_kernel<<<gQKV, 256, HGEMM_SMEM>>>(
            hh, hl, wqh + (size_t)l * QKVC * Dc, wql + (size_t)l * QKVC * Dc,
            nullptr, nullptr, qkv, nullptr, nullptr, nullptr, nullptr,
            NTOK, QKVC, Dc, 0);
        attn_kernel<<<Bc * Hc / 4, 256, ATTN_SMEM>>>(qkv, ah, al);
        // Wo projection + residual + fused LN2
        hgemm_kernel<<<gD, 256, HGEMM_SMEM>>>(
            ah, al, woh + (size_t)l * Dc * Dc, wol + (size_t)l * Dc * Dc,
            bo + l * Dc, x, x, hh, hl, ln2g + l * Dc, ln2b + l * Dc,
            NTOK, Dc, Dc, 0);
        // FFN1 + relu -> hi/lo
        hgemm_kernel<<<gFF, 256, HGEMM_SMEM>>>(
            hh, hl, w1h + (size_t)l * DFFc * Dc, w1l + (size_t)l * DFFc * Dc,
            b1 + l * DFFc, nullptr, nullptr, mh, ml, nullptr, nullptr,
            NTOK, DFFc, Dc, 1);
        // FFN2 + residual + fused LN (next layer's ln1, or lnf)
        const float* ng = (l < Lc - 1) ? (ln1g + (l + 1) * Dc) : lnfg;
        const float* nb = (l < Lc - 1) ? (ln1b + (l + 1) * Dc) : lnfb;
        hgemm_kernel<<<gD, 256, HGEMM_SMEM>>>(
            mh, ml, w2h + (size_t)l * Dc * DFFc, w2l + (size_t)l * Dc * DFFc,
            b2 + l * Dc, x, x, hh, hl, ng, nb,
            NTOK, Dc, DFFc, 0);
    }

    // head
    hgemm_kernel<<<gV, 256, HGEMM_SMEM>>>(
        hh, hl, whh, whl, bhd, nullptr, out, nullptr, nullptr, nullptr, nullptr,
        NTOK, Vc, Dc, 0);
}

// round 11
// speedup vs baseline: 1.1953x; 1.1953x over previous
#include <cuda_runtime.h>
#include <cuda_bf16.h>
#include <cstdint>

// ---------------------------------------------------------------------------
// BigramTransformer forward — HMMA bf16-split GEMMs (K64 chunks, 3 CTA/SM)
// + fused-LN epilogues.  B=2048 T=64 D=128 H=4 HD=32 L=6 V=256 DFF=512
// ---------------------------------------------------------------------------

#define Bc   2048
#define Tc   64
#define Dc   128
#define Hc   4
#define HDc  32
#define Lc   6
#define Vc   256
#define DFFc 512
#define NTOK (Bc * Tc)          /* 131072 */
#define QKVC (3 * Dc)           /* 384    */

// ------------------------- scratch (device globals) ------------------------
__device__ float g_x  [(size_t)NTOK * Dc];
__device__ float g_qkv[(size_t)NTOK * QKVC];
__device__ __nv_bfloat16 g_hh[(size_t)NTOK * Dc],   g_hl[(size_t)NTOK * Dc];
__device__ __nv_bfloat16 g_ah[(size_t)NTOK * Dc],   g_al[(size_t)NTOK * Dc];
__device__ __nv_bfloat16 g_mh[(size_t)NTOK * DFFc], g_ml[(size_t)NTOK * DFFc];
// transposed bf16 weights [N,K] hi/lo
__device__ __nv_bfloat16 g_wqkv_h[Lc * QKVC * Dc],  g_wqkv_l[Lc * QKVC * Dc];
__device__ __nv_bfloat16 g_wo_h  [Lc * Dc * Dc],    g_wo_l  [Lc * Dc * Dc];
__device__ __nv_bfloat16 g_w1_h  [Lc * DFFc * Dc],  g_w1_l  [Lc * DFFc * Dc];
__device__ __nv_bfloat16 g_w2_h  [Lc * Dc * DFFc],  g_w2_l  [Lc * Dc * DFFc];
__device__ __nv_bfloat16 g_whd_h [Vc * Dc],         g_whd_l [Vc * Dc];

// ------------------------- helpers ------------------------------------------
__device__ __forceinline__ uint32_t smem_u32(const void* p) {
    uint32_t a;
    asm("{ .reg .u64 t; cvta.to.shared.u64 t, %1; cvt.u32.u64 %0, t; }"
        : "=r"(a) : "l"(p));
    return a;
}
__device__ __forceinline__ void hilo_store2(float v0, float v1,
                                            __nv_bfloat16* ph, __nv_bfloat16* pl) {
    __nv_bfloat16 h0 = __float2bfloat16(v0), h1 = __float2bfloat16(v1);
    __nv_bfloat162 hh; hh.x = h0; hh.y = h1;
    __nv_bfloat162 ll;
    ll.x = __float2bfloat16(v0 - __bfloat162float(h0));
    ll.y = __float2bfloat16(v1 - __bfloat162float(h1));
    *(__nv_bfloat162*)ph = hh;
    *(__nv_bfloat162*)pl = ll;
}

#define LDMX4(r0, r1, r2, r3, a)                                            \
    asm volatile("ldmatrix.sync.aligned.m8n8.x4.shared.b16 {%0,%1,%2,%3}, [%4];" \
                 : "=r"(r0), "=r"(r1), "=r"(r2), "=r"(r3) : "r"(a))

#define MMA(d, a0, a1, a2, a3, b0v, b1v)                                    \
    asm volatile("mma.sync.aligned.m16n8k16.row.col.f32.bf16.bf16.f32 "     \
                 "{%0,%1,%2,%3}, {%4,%5,%6,%7}, {%8,%9}, {%0,%1,%2,%3};"    \
                 : "+f"((d)[0]), "+f"((d)[1]), "+f"((d)[2]), "+f"((d)[3])   \
                 : "r"(a0), "r"(a1), "r"(a2), "r"(a3), "r"(b0v), "r"(b1v))

#define CP_ASYNC16(dst, src)                                                \
    asm volatile("cp.async.cg.shared.global [%0], [%1], 16;"                \
                 :: "r"(dst), "l"(src))
#define CP_COMMIT() asm volatile("cp.async.commit_group;" ::: "memory")
#define CP_WAIT0()  asm volatile("cp.async.wait_group 0;" ::: "memory")

// ------------------------- weight conversion --------------------------------
__global__ void convw_kernel(const float* __restrict__ W,
                             __nv_bfloat16* __restrict__ oh,
                             __nv_bfloat16* __restrict__ ol, int K, int N)
{
    const size_t base = (size_t)blockIdx.y * K * N;
    int i = blockIdx.x * 256 + threadIdx.x;
    if (i >= K * N) return;
    int k = i / N, n = i % N;
    float v = W[base + i];
    __nv_bfloat16 h = __float2bfloat16(v);
    oh[base + (size_t)n * K + k] = h;
    ol[base + (size_t)n * K + k] = __float2bfloat16(v - __bfloat162float(h));
}

__global__ void convqkv_kernel(const float* __restrict__ Wq,
                               const float* __restrict__ Wk,
                               const float* __restrict__ Wv,
                               __nv_bfloat16* __restrict__ oh,
                               __nv_bfloat16* __restrict__ ol)
{
    int i = blockIdx.x * 256 + threadIdx.x;
    const int total = Lc * Hc * Dc * HDc;
    if (i >= total) return;
    int e = i % HDc;
    int d = (i / HDc) % Dc;
    int h = (i / (HDc * Dc)) % Hc;
    int l = i / (HDc * Dc * Hc);
    int src = ((l * Hc + h) * Dc + d) * HDc + e;
    const float vq = Wq[src], vk = Wk[src], vv = Wv[src];
    const int col = h * HDc + e;
    size_t dq = ((size_t)l * QKVC + col) * Dc + d;
    size_t dk = ((size_t)l * QKVC + Dc + col) * Dc + d;
    size_t dv = ((size_t)l * QKVC + 2 * Dc + col) * Dc + d;
    __nv_bfloat16 hq = __float2bfloat16(vq);
    __nv_bfloat16 hk = __float2bfloat16(vk);
    __nv_bfloat16 hv = __float2bfloat16(vv);
    oh[dq] = hq; ol[dq] = __float2bfloat16(vq - __bfloat162float(hq));
    oh[dk] = hk; ol[dk] = __float2bfloat16(vk - __bfloat162float(hk));
    oh[dv] = hv; ol[dv] = __float2bfloat16(vv - __bfloat162float(hv));
}

// ------------------------- embedding + first LN (warp / token) --------------
__global__ __launch_bounds__(256) void embed_ln_kernel(
    const int* __restrict__ idx,
    const float* __restrict__ tok, const float* __restrict__ pos,
    float* __restrict__ xout,
    __nv_bfloat16* __restrict__ oh, __nv_bfloat16* __restrict__ ol,
    const float* __restrict__ gam, const float* __restrict__ bet)
{
    const int warp = threadIdx.x >> 5;
    const int lane = threadIdx.x & 31;
    const size_t n = (size_t)blockIdx.x * 8 + warp;
    const int t = (int)(n & (Tc - 1));
    const int v = idx[n];

    const float4 tv = ((const float4*)(tok + (size_t)v * Dc))[lane];
    const float4 pv = ((const float4*)(pos + (size_t)t * Dc))[lane];
    float4 x = make_float4(tv.x + pv.x, tv.y + pv.y, tv.z + pv.z, tv.w + pv.w);
    ((float4*)(xout + n * Dc))[lane] = x;

    float s = x.x + x.y + x.z + x.w;
    #pragma unroll
    for (int o = 16; o > 0; o >>= 1) s += __shfl_xor_sync(0xffffffffu, s, o);
    const float mean = s * (1.0f / Dc);

    float4 c = make_float4(x.x - mean, x.y - mean, x.z - mean, x.w - mean);
    float q = c.x * c.x + c.y * c.y + c.z * c.z + c.w * c.w;
    #pragma unroll
    for (int o = 16; o > 0; o >>= 1) q += __shfl_xor_sync(0xffffffffu, q, o);
    const float r = rsqrtf(q * (1.0f / Dc) + 1e-5f);

    const float4 g = ((const float4*)gam)[lane];
    const float4 b = ((const float4*)bet)[lane];
    hilo_store2(c.x * r * g.x + b.x, c.y * r * g.y + b.y,
                oh + n * Dc + lane * 4,     ol + n * Dc + lane * 4);
    hilo_store2(c.z * r * g.z + b.z, c.w * r * g.w + b.w,
                oh + n * Dc + lane * 4 + 2, ol + n * Dc + lane * 4 + 2);
}

// ------------------------- HMMA GEMM (K-chunk 64, 3 CTA/SM) -----------------
// C[M,N] = Ah@Bh^T + Ah@Bl^T + Al@Bh^T (+bias)(relu)(+res)
// lnG!=null (requires N==128, gridDim.x==1): write C to outf and LN(C) hi/lo.
#define TROWB 144                 /* 64 bf16 = 128B + 16B pad        */
#define TILEB (128 * TROWB)       /* 18432B                          */
#define HGEMM_SMEM (4 * TILEB)    /* 73728B -> 3 CTAs/SM             */

__global__ __launch_bounds__(256, 2) void hgemm_kernel(
    const __nv_bfloat16* __restrict__ Ah, const __nv_bfloat16* __restrict__ Al,
    const __nv_bfloat16* __restrict__ Bh, const __nv_bfloat16* __restrict__ Bl,
    const float* __restrict__ bias, const float* __restrict__ res,
    float* __restrict__ outf,
    __nv_bfloat16* __restrict__ outh, __nv_bfloat16* __restrict__ outl,
    const float* __restrict__ lnG, const float* __restrict__ lnB,
    int M, int N, int K, int relu)
{
    extern __shared__ char smem[];
    const uint32_t sb = smem_u32(smem);

    const int tid = threadIdx.x;
    const int w   = tid >> 5;
    const int l   = tid & 31;
    const int wm  = w & 1;
    const int wn  = w >> 1;
    const int m0  = blockIdx.y * 128;
    const int n0  = blockIdx.x * 128;

    const int g    = l >> 3;
    const int idx  = l & 7;
    const int lrow = (g & 1) * 8 + idx;
    const int g2   = (g >> 1) * 16;

    const uint32_t AHo = sb;
    const uint32_t ALo = sb + TILEB;
    const uint32_t BHo = sb + 2 * TILEB;
    const uint32_t BLo = sb + 3 * TILEB;
    const uint32_t arow = (uint32_t)(wm * 64 + lrow) * TROWB + g2;
    const uint32_t brow = (uint32_t)(wn * 32 + lrow) * TROWB + g2;

    const __nv_bfloat16* gsrc[4] = {
        Ah + (size_t)m0 * K, Al + (size_t)m0 * K,
        Bh + (size_t)n0 * K, Bl + (size_t)n0 * K };

    float acc[4][4][4] = {};

    const int nstep = K >> 6;                   // 64-wide K chunks
    for (int c = 0; c < nstep; c++) {
        if (c) __syncthreads();
        const int ck = c << 6;
        // stage 4 tiles: 128 rows x 64 bf16 = 1024 x 16B each, 4 per thread
        #pragma unroll
        for (int t = 0; t < 4; t++) {
            const __nv_bfloat16* src = gsrc[t];
            const uint32_t dst = sb + t * TILEB;
            #pragma unroll
            for (int i = tid; i < 1024; i += 256) {
                const int r  = i >> 3;
                const int c8 = i & 7;
                CP_ASYNC16(dst + r * TROWB + c8 * 16,
                           src + (size_t)r * K + ck + c8 * 8);
            }
        }
        CP_COMMIT();
        CP_WAIT0();
        __syncthreads();

        #pragma unroll
        for (int ks = 0; ks < 4; ks++) {
            const uint32_t kb = ks * 32;
            uint32_t bh_[2][4], bl_[2][4];
            #pragma unroll
            for (int p = 0; p < 2; p++) {
                const uint32_t bo = brow + p * (16 * TROWB) + kb;
                LDMX4(bh_[p][0], bh_[p][1], bh_[p][2], bh_[p][3], BHo + bo);
                LDMX4(bl_[p][0], bl_[p][1], bl_[p][2], bl_[p][3], BLo + bo);
            }
            #pragma unroll
            for (int mt = 0; mt < 4; mt++) {
                const uint32_t ao = arow + mt * (16 * TROWB) + kb;
                uint32_t a0, a1, a2, a3, x0, x1, x2, x3;
                LDMX4(a0, a1, a2, a3, AHo + ao);
                LDMX4(x0, x1, x2, x3, ALo + ao);
                #pragma unroll
                for (int nt = 0; nt < 4; nt++) {
                    const int p = nt >> 1, q = nt & 1;
                    const uint32_t b0h = bh_[p][q], b1h = bh_[p][q + 2];
                    const uint32_t b0l = bl_[p][q], b1l = bl_[p][q + 2];
                    MMA(acc[mt][nt], a0, a1, a2, a3, b0h, b1h);
                    MMA(acc[mt][nt], a0, a1, a2, a3, b0l, b1l);
                    MMA(acc[mt][nt], x0, x1, x2, x3, b0h, b1h);
                }
            }
        }
    }

    const int gr = l >> 2;
    const int gc = (l & 3) * 2;

    if (lnG) {
        // ---- fused epilogue: bias + residual + LN over the 128-wide row ----
        __syncthreads();                         // tiles dead; reuse smem
        float* sums  = (float*)smem;             // [128][4]
        float* sumsq = (float*)smem + 512;       // [128][4]

        #pragma unroll
        for (int mt = 0; mt < 4; mt++) {
            #pragma unroll
            for (int h = 0; h < 2; h++) {
                const int r64 = wm * 64 + mt * 16 + gr + h * 8;
                const size_t row = (size_t)m0 + r64;
                float s = 0.f, q = 0.f;
                #pragma unroll
                for (int nt = 0; nt < 4; nt++) {
                    const int n = wn * 32 + nt * 8 + gc;
                    float v0 = acc[mt][nt][h * 2];
                    float v1 = acc[mt][nt][h * 2 + 1];
                    const float2 bb = *(const float2*)(bias + n);
                    v0 += bb.x; v1 += bb.y;
                    const float2 rr = *(const float2*)(res + row * Dc + n);
                    v0 += rr.x; v1 += rr.y;
                    acc[mt][nt][h * 2]     = v0;
                    acc[mt][nt][h * 2 + 1] = v1;
                    *(float2*)(outf + row * Dc + n) = make_float2(v0, v1);
                    s += v0 + v1;
                    q += v0 * v0 + v1 * v1;
                }
                s += __shfl_xor_sync(0xffffffffu, s, 1);
                s += __shfl_xor_sync(0xffffffffu, s, 2);
                q += __shfl_xor_sync(0xffffffffu, q, 1);
                q += __shfl_xor_sync(0xffffffffu, q, 2);
                if ((l & 3) == 0) {
                    sums [r64 * 4 + wn] = s;
                    sumsq[r64 * 4 + wn] = q;
                }
            }
        }
        __syncthreads();
        #pragma unroll
        for (int mt = 0; mt < 4; mt++) {
            #pragma unroll
            for (int h = 0; h < 2; h++) {
                const int r64 = wm * 64 + mt * 16 + gr + h * 8;
                const size_t row = (size_t)m0 + r64;
                float S = sums[r64 * 4] + sums[r64 * 4 + 1]
                        + sums[r64 * 4 + 2] + sums[r64 * 4 + 3];
                float Q = sumsq[r64 * 4] + sumsq[r64 * 4 + 1]
                        + sumsq[r64 * 4 + 2] + sumsq[r64 * 4 + 3];
                const float mean = S * (1.0f / Dc);
                const float var  = Q * (1.0f / Dc) - mean * mean;
                const float rst  = rsqrtf(var + 1e-5f);
                #pragma unroll
                for (int nt = 0; nt < 4; nt++) {
                    const int n = wn * 32 + nt * 8 + gc;
                    const float2 gg = *(const float2*)(lnG + n);
                    const float2 bb = *(const float2*)(lnB + n);
                    const float v0 = acc[mt][nt][h * 2];
                    const float v1 = acc[mt][nt][h * 2 + 1];
                    hilo_store2((v0 - mean) * rst * gg.x + bb.x,
                                (v1 - mean) * rst * gg.y + bb.y,
                                outh + row * Dc + n, outl + row * Dc + n);
                }
            }
        }
        return;
    }

    // ---- plain epilogue ----
    #pragma unroll
    for (int mt = 0; mt < 4; mt++) {
        #pragma unroll
        for (int h = 0; h < 2; h++) {
            const size_t row = (size_t)m0 + wm * 64 + mt * 16 + gr + h * 8;
            #pragma unroll
            for (int nt = 0; nt < 4; nt++) {
                const int n = n0 + wn * 32 + nt * 8 + gc;
                float v0 = acc[mt][nt][h * 2];
                float v1 = acc[mt][nt][h * 2 + 1];
                if (bias) {
                    const float2 bb = *(const float2*)(bias + n);
                    v0 += bb.x; v1 += bb.y;
                }
                if (relu) { v0 = fmaxf(v0, 0.f); v1 = fmaxf(v1, 0.f); }
                if (outh) {
                    hilo_store2(v0, v1, outh + row * N + n, outl + row * N + n);
                } else {
                    *(float2*)(outf + row * N + n) = make_float2(v0, v1);
                }
            }
        }
    }
}

// ------------------------- attention: one block per (b,h) -------------------
__global__ __launch_bounds__(Tc) void attn_kernel(const float* __restrict__ qkv,
                                                  __nv_bfloat16* __restrict__ oh,
                                                  __nv_bfloat16* __restrict__ ol)
{
    __shared__ float4 qsm[Tc][HDc / 4];
    __shared__ float4 ksm[Tc][HDc / 4];
    __shared__ float4 vsm[Tc][HDc / 4];

    const int bh  = blockIdx.x;
    const int b   = bh >> 2;
    const int h   = bh & 3;
    const int tid = threadIdx.x;

    const float* row = qkv + ((size_t)(b * Tc + tid)) * QKVC + h * HDc;
    #pragma unroll
    for (int j = 0; j < 8; j++) {
        qsm[tid][j] = *(const float4*)(row + 4 * j);
        ksm[tid][j] = *(const float4*)(row + Dc + 4 * j);
        vsm[tid][j] = *(const float4*)(row + 2 * Dc + 4 * j);
    }
    __syncthreads();

    const int t = tid;
    float q[HDc];
    #pragma unroll
    for (int j = 0; j < 8; j++) {
        float4 f = qsm[t][j];
        q[4 * j] = f.x; q[4 * j + 1] = f.y; q[4 * j + 2] = f.z; q[4 * j + 3] = f.w;
    }

    const float scale = 0.17677669529663687f;
    float sc[Tc];
    float mx = -1e30f;
    #pragma unroll
    for (int s = 0; s < Tc; s++) {
        float d = 0.f;
        #pragma unroll
        for (int j = 0; j < 8; j++) {
            float4 f = ksm[s][j];
            d = fmaf(q[4 * j],     f.x, d);
            d = fmaf(q[4 * j + 1], f.y, d);
            d = fmaf(q[4 * j + 2], f.z, d);
            d = fmaf(q[4 * j + 3], f.w, d);
        }
        d *= scale;
        sc[s] = d;
        if (s <= t) mx = fmaxf(mx, d);
    }

    float sum = 0.f;
    #pragma unroll
    for (int s = 0; s < Tc; s++) {
        float w = (s <= t) ? __expf(sc[s] - mx) : 0.f;
        sc[s] = w;
        sum += w;
    }
    const float inv = 1.f / sum;

    float4 acc[8] = {};
    #pragma unroll
    for (int s = 0; s < Tc; s++) {
        float w = sc[s];
        #pragma unroll
        for (int j = 0; j < 8; j++) {
            float4 f = vsm[s][j];
            acc[j].x = fmaf(w, f.x, acc[j].x);
            acc[j].y = fmaf(w, f.y, acc[j].y);
            acc[j].z = fmaf(w, f.z, acc[j].z);
            acc[j].w = fmaf(w, f.w, acc[j].w);
        }
    }

    const size_t base = ((size_t)(b * Tc + t)) * Dc + h * HDc;
    #pragma unroll
    for (int j = 0; j < 8; j++) {
        float4 o = acc[j];
        o.x *= inv; o.y *= inv; o.z *= inv; o.w *= inv;
        hilo_store2(o.x, o.y, oh + base + 4 * j,     ol + base + 4 * j);
        hilo_store2(o.z, o.w, oh + base + 4 * j + 2, ol + base + 4 * j + 2);
    }
}

// ------------------------- launcher -----------------------------------------
extern "C" void kernel_launch(void* const* d_in, const int* in_sizes, int n_in,
                              void* d_out, int out_size)
{
    (void)in_sizes; (void)n_in; (void)out_size;
    const int*   idx  = (const int*)  d_in[0];
    const float* tok  = (const float*)d_in[1];
    const float* pos  = (const float*)d_in[2];
    const float* Wq   = (const float*)d_in[3];
    const float* Wk   = (const float*)d_in[4];
    const float* Wv   = (const float*)d_in[5];
    const float* Wo   = (const float*)d_in[6];
    const float* bo   = (const float*)d_in[7];
    const float* ln1g = (const float*)d_in[8];
    const float* ln1b = (const float*)d_in[9];
    const float* W1   = (const float*)d_in[10];
    const float* b1   = (const float*)d_in[11];
    const float* W2   = (const float*)d_in[12];
    const float* b2   = (const float*)d_in[13];
    const float* ln2g = (const float*)d_in[14];
    const float* ln2b = (const float*)d_in[15];
    const float* lnfg = (const float*)d_in[16];
    const float* lnfb = (const float*)d_in[17];
    const float* Wh   = (const float*)d_in[18];
    const float* bhd  = (const float*)d_in[19];
    float* out = (float*)d_out;

    float *x, *qkv;
    __nv_bfloat16 *hh, *hl, *ah, *al, *mh, *ml;
    __nv_bfloat16 *wqh, *wql, *woh, *wol, *w1h, *w1l, *w2h, *w2l, *whh, *whl;
    cudaGetSymbolAddress((void**)&x,   g_x);
    cudaGetSymbolAddress((void**)&qkv, g_qkv);
    cudaGetSymbolAddress((void**)&hh,  g_hh);  cudaGetSymbolAddress((void**)&hl, g_hl);
    cudaGetSymbolAddress((void**)&ah,  g_ah);  cudaGetSymbolAddress((void**)&al, g_al);
    cudaGetSymbolAddress((void**)&mh,  g_mh);  cudaGetSymbolAddress((void**)&ml, g_ml);
    cudaGetSymbolAddress((void**)&wqh, g_wqkv_h); cudaGetSymbolAddress((void**)&wql, g_wqkv_l);
    cudaGetSymbolAddress((void**)&woh, g_wo_h);   cudaGetSymbolAddress((void**)&wol, g_wo_l);
    cudaGetSymbolAddress((void**)&w1h, g_w1_h);   cudaGetSymbolAddress((void**)&w1l, g_w1_l);
    cudaGetSymbolAddress((void**)&w2h, g_w2_h);   cudaGetSymbolAddress((void**)&w2l, g_w2_l);
    cudaGetSymbolAddress((void**)&whh, g_whd_h);  cudaGetSymbolAddress((void**)&whl, g_whd_l);

    cudaFuncSetAttribute(hgemm_kernel,
                         cudaFuncAttributeMaxDynamicSharedMemorySize, HGEMM_SMEM);

    // weight conversion
    convqkv_kernel<<<(Lc * Hc * Dc * HDc + 255) / 256, 256>>>(Wq, Wk, Wv, wqh, wql);
    convw_kernel<<<dim3((Dc * Dc + 255) / 256, Lc), 256>>>(Wo, woh, wol, Dc, Dc);
    convw_kernel<<<dim3((Dc * DFFc + 255) / 256, Lc), 256>>>(W1, w1h, w1l, Dc, DFFc);
    convw_kernel<<<dim3((DFFc * Dc + 255) / 256, Lc), 256>>>(W2, w2h, w2l, DFFc, Dc);
    convw_kernel<<<dim3((Dc * Vc + 255) / 256, 1), 256>>>(Wh, whh, whl, Dc, Vc);

    // embed + ln1 of layer 0
    embed_ln_kernel<<<NTOK / 8, 256>>>(idx, tok, pos, x, hh, hl, ln1g, ln1b);

    const int MT = NTOK / 128;
    const dim3 gQKV(QKVC / 128, MT);
    const dim3 gD  (1,          MT);
    const dim3 gFF (DFFc / 128, MT);
    const dim3 gV  (Vc   / 128, MT);

    for (int l = 0; l < Lc; l++) {
        hgemm_kernel<<<gQKV, 256, HGEMM_SMEM>>>(
            hh, hl, wqh + (size_t)l * QKVC * Dc, wql + (size_t)l * QKVC * Dc,
            nullptr, nullptr, qkv, nullptr, nullptr, nullptr, nullptr,
            NTOK, QKVC, Dc, 0);
        attn_kernel<<<Bc * Hc, Tc>>>(qkv, ah, al);
        hgemm_kernel<<<gD, 256, HGEMM_SMEM>>>(
            ah, al, woh + (size_t)l * Dc * Dc, wol + (size_t)l * Dc * Dc,
            bo + l * Dc, x, x, hh, hl, ln2g + l * Dc, ln2b + l * Dc,
            NTOK, Dc, Dc, 0);
        hgemm_kernel<<<gFF, 256, HGEMM_SMEM>>>(
            hh, hl, w1h + (size_t)l * DFFc * Dc, w1l + (size_t)l * DFFc * Dc,
            b1 + l * DFFc, nullptr, nullptr, mh, ml, nullptr, nullptr,
            NTOK, DFFc, Dc, 1);
        const float* ng = (l < Lc - 1) ? (ln1g + (l + 1) * Dc) : lnfg;
        const float* nb = (l < Lc - 1) ? (ln1b + (l + 1) * Dc) : lnfb;
        hgemm_kernel<<<gD, 256, HGEMM_SMEM>>>(
            mh, ml, w2h + (size_t)l * Dc * DFFc, w2l + (size_t)l * Dc * DFFc,
            b2 + l * Dc, x, x, hh, hl, ng, nb,
            NTOK, Dc, DFFc, 0);
    }

    hgemm_kernel<<<gV, 256, HGEMM_SMEM>>>(
        hh, hl, whh, whl, bhd, nullptr, out, nullptr, nullptr, nullptr, nullptr,
        NTOK, Vc, Dc, 0);
}

// round 12
// speedup vs baseline: 1.3074x; 1.0938x over previous
#include <cuda_runtime.h>
#include <cuda_bf16.h>
#include <cstdint>

// ---------------------------------------------------------------------------
// BigramTransformer forward — HMMA bf16-split GEMMs (K64 chunks, 2 CTA/SM)
// + fused-LN epilogues + 4-thread/row attention.
// B=2048 T=64 D=128 H=4 HD=32 L=6 V=256 DFF=512
// ---------------------------------------------------------------------------

#define Bc   2048
#define Tc   64
#define Dc   128
#define Hc   4
#define HDc  32
#define Lc   6
#define Vc   256
#define DFFc 512
#define NTOK (Bc * Tc)          /* 131072 */
#define QKVC (3 * Dc)           /* 384    */

// ------------------------- scratch (device globals) ------------------------
__device__ float g_x  [(size_t)NTOK * Dc];
__device__ float g_qkv[(size_t)NTOK * QKVC];
__device__ __nv_bfloat16 g_hh[(size_t)NTOK * Dc],   g_hl[(size_t)NTOK * Dc];
__device__ __nv_bfloat16 g_ah[(size_t)NTOK * Dc],   g_al[(size_t)NTOK * Dc];
__device__ __nv_bfloat16 g_mh[(size_t)NTOK * DFFc], g_ml[(size_t)NTOK * DFFc];
// transposed bf16 weights [N,K] hi/lo
__device__ __nv_bfloat16 g_wqkv_h[Lc * QKVC * Dc],  g_wqkv_l[Lc * QKVC * Dc];
__device__ __nv_bfloat16 g_wo_h  [Lc * Dc * Dc],    g_wo_l  [Lc * Dc * Dc];
__device__ __nv_bfloat16 g_w1_h  [Lc * DFFc * Dc],  g_w1_l  [Lc * DFFc * Dc];
__device__ __nv_bfloat16 g_w2_h  [Lc * Dc * DFFc],  g_w2_l  [Lc * Dc * DFFc];
__device__ __nv_bfloat16 g_whd_h [Vc * Dc],         g_whd_l [Vc * Dc];

// ------------------------- helpers ------------------------------------------
__device__ __forceinline__ uint32_t smem_u32(const void* p) {
    uint32_t a;
    asm("{ .reg .u64 t; cvta.to.shared.u64 t, %1; cvt.u32.u64 %0, t; }"
        : "=r"(a) : "l"(p));
    return a;
}
__device__ __forceinline__ void hilo_store2(float v0, float v1,
                                            __nv_bfloat16* ph, __nv_bfloat16* pl) {
    __nv_bfloat16 h0 = __float2bfloat16(v0), h1 = __float2bfloat16(v1);
    __nv_bfloat162 hh; hh.x = h0; hh.y = h1;
    __nv_bfloat162 ll;
    ll.x = __float2bfloat16(v0 - __bfloat162float(h0));
    ll.y = __float2bfloat16(v1 - __bfloat162float(h1));
    *(__nv_bfloat162*)ph = hh;
    *(__nv_bfloat162*)pl = ll;
}

#define LDMX4(r0, r1, r2, r3, a)                                            \
    asm volatile("ldmatrix.sync.aligned.m8n8.x4.shared.b16 {%0,%1,%2,%3}, [%4];" \
                 : "=r"(r0), "=r"(r1), "=r"(r2), "=r"(r3) : "r"(a))

#define MMA(d, a0, a1, a2, a3, b0v, b1v)                                    \
    asm volatile("mma.sync.aligned.m16n8k16.row.col.f32.bf16.bf16.f32 "     \
                 "{%0,%1,%2,%3}, {%4,%5,%6,%7}, {%8,%9}, {%0,%1,%2,%3};"    \
                 : "+f"((d)[0]), "+f"((d)[1]), "+f"((d)[2]), "+f"((d)[3])   \
                 : "r"(a0), "r"(a1), "r"(a2), "r"(a3), "r"(b0v), "r"(b1v))

#define CP_ASYNC16(dst, src)                                                \
    asm volatile("cp.async.cg.shared.global [%0], [%1], 16;"                \
                 :: "r"(dst), "l"(src))
#define CP_COMMIT() asm volatile("cp.async.commit_group;" ::: "memory")
#define CP_WAIT0()  asm volatile("cp.async.wait_group 0;" ::: "memory")

// ------------------------- weight conversion --------------------------------
__global__ void convw_kernel(const float* __restrict__ W,
                             __nv_bfloat16* __restrict__ oh,
                             __nv_bfloat16* __restrict__ ol, int K, int N)
{
    const size_t base = (size_t)blockIdx.y * K * N;
    int i = blockIdx.x * 256 + threadIdx.x;
    if (i >= K * N) return;
    int k = i / N, n = i % N;
    float v = W[base + i];
    __nv_bfloat16 h = __float2bfloat16(v);
    oh[base + (size_t)n * K + k] = h;
    ol[base + (size_t)n * K + k] = __float2bfloat16(v - __bfloat162float(h));
}

__global__ void convqkv_kernel(const float* __restrict__ Wq,
                               const float* __restrict__ Wk,
                               const float* __restrict__ Wv,
                               __nv_bfloat16* __restrict__ oh,
                               __nv_bfloat16* __restrict__ ol)
{
    int i = blockIdx.x * 256 + threadIdx.x;
    const int total = Lc * Hc * Dc * HDc;
    if (i >= total) return;
    int e = i % HDc;
    int d = (i / HDc) % Dc;
    int h = (i / (HDc * Dc)) % Hc;
    int l = i / (HDc * Dc * Hc);
    int src = ((l * Hc + h) * Dc + d) * HDc + e;
    const float vq = Wq[src], vk = Wk[src], vv = Wv[src];
    const int col = h * HDc + e;
    size_t dq = ((size_t)l * QKVC + col) * Dc + d;
    size_t dk = ((size_t)l * QKVC + Dc + col) * Dc + d;
    size_t dv = ((size_t)l * QKVC + 2 * Dc + col) * Dc + d;
    __nv_bfloat16 hq = __float2bfloat16(vq);
    __nv_bfloat16 hk = __float2bfloat16(vk);
    __nv_bfloat16 hv = __float2bfloat16(vv);
    oh[dq] = hq; ol[dq] = __float2bfloat16(vq - __bfloat162float(hq));
    oh[dk] = hk; ol[dk] = __float2bfloat16(vk - __bfloat162float(hk));
    oh[dv] = hv; ol[dv] = __float2bfloat16(vv - __bfloat162float(hv));
}

// ------------------------- embedding + first LN (warp / token) --------------
__global__ __launch_bounds__(256) void embed_ln_kernel(
    const int* __restrict__ idx,
    const float* __restrict__ tok, const float* __restrict__ pos,
    float* __restrict__ xout,
    __nv_bfloat16* __restrict__ oh, __nv_bfloat16* __restrict__ ol,
    const float* __restrict__ gam, const float* __restrict__ bet)
{
    const int warp = threadIdx.x >> 5;
    const int lane = threadIdx.x & 31;
    const size_t n = (size_t)blockIdx.x * 8 + warp;
    const int t = (int)(n & (Tc - 1));
    const int v = idx[n];

    const float4 tv = ((const float4*)(tok + (size_t)v * Dc))[lane];
    const float4 pv = ((const float4*)(pos + (size_t)t * Dc))[lane];
    float4 x = make_float4(tv.x + pv.x, tv.y + pv.y, tv.z + pv.z, tv.w + pv.w);
    ((float4*)(xout + n * Dc))[lane] = x;

    float s = x.x + x.y + x.z + x.w;
    #pragma unroll
    for (int o = 16; o > 0; o >>= 1) s += __shfl_xor_sync(0xffffffffu, s, o);
    const float mean = s * (1.0f / Dc);

    float4 c = make_float4(x.x - mean, x.y - mean, x.z - mean, x.w - mean);
    float q = c.x * c.x + c.y * c.y + c.z * c.z + c.w * c.w;
    #pragma unroll
    for (int o = 16; o > 0; o >>= 1) q += __shfl_xor_sync(0xffffffffu, q, o);
    const float r = rsqrtf(q * (1.0f / Dc) + 1e-5f);

    const float4 g = ((const float4*)gam)[lane];
    const float4 b = ((const float4*)bet)[lane];
    hilo_store2(c.x * r * g.x + b.x, c.y * r * g.y + b.y,
                oh + n * Dc + lane * 4,     ol + n * Dc + lane * 4);
    hilo_store2(c.z * r * g.z + b.z, c.w * r * g.w + b.w,
                oh + n * Dc + lane * 4 + 2, ol + n * Dc + lane * 4 + 2);
}

// ------------------------- HMMA GEMM (K-chunk 64) ---------------------------
#define TROWB 144
#define TILEB (128 * TROWB)
#define HGEMM_SMEM (4 * TILEB)

__global__ __launch_bounds__(256, 2) void hgemm_kernel(
    const __nv_bfloat16* __restrict__ Ah, const __nv_bfloat16* __restrict__ Al,
    const __nv_bfloat16* __restrict__ Bh, const __nv_bfloat16* __restrict__ Bl,
    const float* __restrict__ bias, const float* __restrict__ res,
    float* __restrict__ outf,
    __nv_bfloat16* __restrict__ outh, __nv_bfloat16* __restrict__ outl,
    const float* __restrict__ lnG, const float* __restrict__ lnB,
    int M, int N, int K, int relu)
{
    extern __shared__ char smem[];
    const uint32_t sb = smem_u32(smem);

    const int tid = threadIdx.x;
    const int w   = tid >> 5;
    const int l   = tid & 31;
    const int wm  = w & 1;
    const int wn  = w >> 1;
    const int m0  = blockIdx.y * 128;
    const int n0  = blockIdx.x * 128;

    const int g    = l >> 3;
    const int idx  = l & 7;
    const int lrow = (g & 1) * 8 + idx;
    const int g2   = (g >> 1) * 16;

    const uint32_t AHo = sb;
    const uint32_t ALo = sb + TILEB;
    const uint32_t BHo = sb + 2 * TILEB;
    const uint32_t BLo = sb + 3 * TILEB;
    const uint32_t arow = (uint32_t)(wm * 64 + lrow) * TROWB + g2;
    const uint32_t brow = (uint32_t)(wn * 32 + lrow) * TROWB + g2;

    const __nv_bfloat16* gsrc[4] = {
        Ah + (size_t)m0 * K, Al + (size_t)m0 * K,
        Bh + (size_t)n0 * K, Bl + (size_t)n0 * K };

    float acc[4][4][4] = {};

    const int nstep = K >> 6;
    for (int c = 0; c < nstep; c++) {
        if (c) __syncthreads();
        const int ck = c << 6;
        #pragma unroll
        for (int t = 0; t < 4; t++) {
            const __nv_bfloat16* src = gsrc[t];
            const uint32_t dst = sb + t * TILEB;
            #pragma unroll
            for (int i = tid; i < 1024; i += 256) {
                const int r  = i >> 3;
                const int c8 = i & 7;
                CP_ASYNC16(dst + r * TROWB + c8 * 16,
                           src + (size_t)r * K + ck + c8 * 8);
            }
        }
        CP_COMMIT();
        CP_WAIT0();
        __syncthreads();

        #pragma unroll
        for (int ks = 0; ks < 4; ks++) {
            const uint32_t kb = ks * 32;
            uint32_t bh_[2][4], bl_[2][4];
            #pragma unroll
            for (int p = 0; p < 2; p++) {
                const uint32_t bo = brow + p * (16 * TROWB) + kb;
                LDMX4(bh_[p][0], bh_[p][1], bh_[p][2], bh_[p][3], BHo + bo);
                LDMX4(bl_[p][0], bl_[p][1], bl_[p][2], bl_[p][3], BLo + bo);
            }
            #pragma unroll
            for (int mt = 0; mt < 4; mt++) {
                const uint32_t ao = arow + mt * (16 * TROWB) + kb;
                uint32_t a0, a1, a2, a3, x0, x1, x2, x3;
                LDMX4(a0, a1, a2, a3, AHo + ao);
                LDMX4(x0, x1, x2, x3, ALo + ao);
                #pragma unroll
                for (int nt = 0; nt < 4; nt++) {
                    const int p = nt >> 1, q = nt & 1;
                    const uint32_t b0h = bh_[p][q], b1h = bh_[p][q + 2];
                    const uint32_t b0l = bl_[p][q], b1l = bl_[p][q + 2];
                    MMA(acc[mt][nt], a0, a1, a2, a3, b0h, b1h);
                    MMA(acc[mt][nt], a0, a1, a2, a3, b0l, b1l);
                    MMA(acc[mt][nt], x0, x1, x2, x3, b0h, b1h);
                }
            }
        }
    }

    const int gr = l >> 2;
    const int gc = (l & 3) * 2;

    if (lnG) {
        __syncthreads();
        float* sums  = (float*)smem;
        float* sumsq = (float*)smem + 512;

        #pragma unroll
        for (int mt = 0; mt < 4; mt++) {
            #pragma unroll
            for (int h = 0; h < 2; h++) {
                const int r64 = wm * 64 + mt * 16 + gr + h * 8;
                const size_t row = (size_t)m0 + r64;
                float s = 0.f, q = 0.f;
                #pragma unroll
                for (int nt = 0; nt < 4; nt++) {
                    const int n = wn * 32 + nt * 8 + gc;
                    float v0 = acc[mt][nt][h * 2];
                    float v1 = acc[mt][nt][h * 2 + 1];
                    const float2 bb = *(const float2*)(bias + n);
                    v0 += bb.x; v1 += bb.y;
                    const float2 rr = *(const float2*)(res + row * Dc + n);
                    v0 += rr.x; v1 += rr.y;
                    acc[mt][nt][h * 2]     = v0;
                    acc[mt][nt][h * 2 + 1] = v1;
                    *(float2*)(outf + row * Dc + n) = make_float2(v0, v1);
                    s += v0 + v1;
                    q += v0 * v0 + v1 * v1;
                }
                s += __shfl_xor_sync(0xffffffffu, s, 1);
                s += __shfl_xor_sync(0xffffffffu, s, 2);
                q += __shfl_xor_sync(0xffffffffu, q, 1);
                q += __shfl_xor_sync(0xffffffffu, q, 2);
                if ((l & 3) == 0) {
                    sums [r64 * 4 + wn] = s;
                    sumsq[r64 * 4 + wn] = q;
                }
            }
        }
        __syncthreads();
        #pragma unroll
        for (int mt = 0; mt < 4; mt++) {
            #pragma unroll
            for (int h = 0; h < 2; h++) {
                const int r64 = wm * 64 + mt * 16 + gr + h * 8;
                const size_t row = (size_t)m0 + r64;
                float S = sums[r64 * 4] + sums[r64 * 4 + 1]
                        + sums[r64 * 4 + 2] + sums[r64 * 4 + 3];
                float Q = sumsq[r64 * 4] + sumsq[r64 * 4 + 1]
                        + sumsq[r64 * 4 + 2] + sumsq[r64 * 4 + 3];
                const float mean = S * (1.0f / Dc);
                const float var  = Q * (1.0f / Dc) - mean * mean;
                const float rst  = rsqrtf(var + 1e-5f);
                #pragma unroll
                for (int nt = 0; nt < 4; nt++) {
                    const int n = wn * 32 + nt * 8 + gc;
                    const float2 gg = *(const float2*)(lnG + n);
                    const float2 bb = *(const float2*)(lnB + n);
                    const float v0 = acc[mt][nt][h * 2];
                    const float v1 = acc[mt][nt][h * 2 + 1];
                    hilo_store2((v0 - mean) * rst * gg.x + bb.x,
                                (v1 - mean) * rst * gg.y + bb.y,
                                outh + row * Dc + n, outl + row * Dc + n);
                }
            }
        }
        return;
    }

    #pragma unroll
    for (int mt = 0; mt < 4; mt++) {
        #pragma unroll
        for (int h = 0; h < 2; h++) {
            const size_t row = (size_t)m0 + wm * 64 + mt * 16 + gr + h * 8;
            #pragma unroll
            for (int nt = 0; nt < 4; nt++) {
                const int n = n0 + wn * 32 + nt * 8 + gc;
                float v0 = acc[mt][nt][h * 2];
                float v1 = acc[mt][nt][h * 2 + 1];
                if (bias) {
                    const float2 bb = *(const float2*)(bias + n);
                    v0 += bb.x; v1 += bb.y;
                }
                if (relu) { v0 = fmaxf(v0, 0.f); v1 = fmaxf(v1, 0.f); }
                if (outh) {
                    hilo_store2(v0, v1, outh + row * N + n, outl + row * N + n);
                } else {
                    *(float2*)(outf + row * N + n) = make_float2(v0, v1);
                }
            }
        }
    }
}

// ------------------------- attention: 4 threads per row ---------------------
// Block = 256 threads = one (b,h). thread (row=tid>>2, sub=tid&3):
//   phase 1: scores s = sub + 4*i (i<16), shfl-reduced softmax, weights to smem
//   phase 2: output dims d = sub*8..sub*8+7 over s<=row.
#define QKP 36          /* padded row stride (floats) for q/k/v */
#define WMP 68          /* padded row stride (floats) for weights */
__global__ __launch_bounds__(256) void attn_kernel(const float* __restrict__ qkv,
                                                   __nv_bfloat16* __restrict__ oh,
                                                   __nv_bfloat16* __restrict__ ol)
{
    __shared__ float qs[Tc][QKP];
    __shared__ float ks[Tc][QKP];
    __shared__ float vs[Tc][QKP];
    __shared__ float wm[Tc][WMP];

    const int bh  = blockIdx.x;
    const int b   = bh >> 2;
    const int h   = bh & 3;
    const int tid = threadIdx.x;

    // load q,k,v: 64 rows x 8 float4 per matrix
    for (int i = tid; i < 3 * Tc * 8; i += 256) {
        const int mat = i >> 9;            // 0..2  (512 float4 per matrix)
        const int r   = (i >> 3) & 63;
        const int j   = i & 7;
        const float4 val = *(const float4*)(qkv + ((size_t)(b * Tc + r)) * QKVC
                                            + mat * Dc + h * HDc + 4 * j);
        float* dst = (mat == 0) ? &qs[r][4 * j] : (mat == 1) ? &ks[r][4 * j]
                                                             : &vs[r][4 * j];
        *(float4*)dst = val;
    }
    __syncthreads();

    const int row = tid >> 2;
    const int sub = tid & 3;
    const float scale = 0.17677669529663687f;

    float qr[HDc];
    #pragma unroll
    for (int j = 0; j < HDc; j += 4) {
        const float4 f = *(const float4*)&qs[row][j];
        qr[j] = f.x; qr[j + 1] = f.y; qr[j + 2] = f.z; qr[j + 3] = f.w;
    }

    float wv[16];
    float mx = -1e30f;
    #pragma unroll
    for (int i = 0; i < 16; i++) {
        const int s = sub + 4 * i;
        float d = 0.f;
        #pragma unroll
        for (int j = 0; j < HDc; j += 4) {
            const float4 f = *(const float4*)&ks[s][j];
            d = fmaf(qr[j],     f.x, d);
            d = fmaf(qr[j + 1], f.y, d);
            d = fmaf(qr[j + 2], f.z, d);
            d = fmaf(qr[j + 3], f.w, d);
        }
        d *= scale;
        wv[i] = d;
        if (s <= row) mx = fmaxf(mx, d);
    }
    mx = fmaxf(mx, __shfl_xor_sync(0xffffffffu, mx, 1));
    mx = fmaxf(mx, __shfl_xor_sync(0xffffffffu, mx, 2));

    float sum = 0.f;
    #pragma unroll
    for (int i = 0; i < 16; i++) {
        const int s = sub + 4 * i;
        const float e = (s <= row) ? __expf(wv[i] - mx) : 0.f;
        wv[i] = e;
        sum += e;
    }
    sum += __shfl_xor_sync(0xffffffffu, sum, 1);
    sum += __shfl_xor_sync(0xffffffffu, sum, 2);
    const float inv = 1.f / sum;

    #pragma unroll
    for (int i = 0; i < 16; i++)
        wm[row][sub + 4 * i] = wv[i] * inv;
    __syncthreads();

    // phase 2: 8 output dims per thread
    const int d0 = sub * 8;
    float acc[8] = {};
    for (int s = 0; s <= row; s++) {
        const float wgt = wm[row][s];
        const float4 v0 = *(const float4*)&vs[s][d0];
        const float4 v1 = *(const float4*)&vs[s][d0 + 4];
        acc[0] = fmaf(wgt, v0.x, acc[0]);
        acc[1] = fmaf(wgt, v0.y, acc[1]);
        acc[2] = fmaf(wgt, v0.z, acc[2]);
        acc[3] = fmaf(wgt, v0.w, acc[3]);
        acc[4] = fmaf(wgt, v1.x, acc[4]);
        acc[5] = fmaf(wgt, v1.y, acc[5]);
        acc[6] = fmaf(wgt, v1.z, acc[6]);
        acc[7] = fmaf(wgt, v1.w, acc[7]);
    }

    const size_t base = ((size_t)(b * Tc + row)) * Dc + h * HDc + d0;
    #pragma unroll
    for (int j = 0; j < 8; j += 2)
        hilo_store2(acc[j], acc[j + 1], oh + base + j, ol + base + j);
}

// ------------------------- launcher -----------------------------------------
extern "C" void kernel_launch(void* const* d_in, const int* in_sizes, int n_in,
                              void* d_out, int out_size)
{
    (void)in_sizes; (void)n_in; (void)out_size;
    const int*   idx  = (const int*)  d_in[0];
    const float* tok  = (const float*)d_in[1];
    const float* pos  = (const float*)d_in[2];
    const float* Wq   = (const float*)d_in[3];
    const float* Wk   = (const float*)d_in[4];
    const float* Wv   = (const float*)d_in[5];
    const float* Wo   = (const float*)d_in[6];
    const float* bo   = (const float*)d_in[7];
    const float* ln1g = (const float*)d_in[8];
    const float* ln1b = (const float*)d_in[9];
    const float* W1   = (const float*)d_in[10];
    const float* b1   = (const float*)d_in[11];
    const float* W2   = (const float*)d_in[12];
    const float* b2   = (const float*)d_in[13];
    const float* ln2g = (const float*)d_in[14];
    const float* ln2b = (const float*)d_in[15];
    const float* lnfg = (const float*)d_in[16];
    const float* lnfb = (const float*)d_in[17];
    const float* Wh   = (const float*)d_in[18];
    const float* bhd  = (const float*)d_in[19];
    float* out = (float*)d_out;

    float *x, *qkv;
    __nv_bfloat16 *hh, *hl, *ah, *al, *mh, *ml;
    __nv_bfloat16 *wqh, *wql, *woh, *wol, *w1h, *w1l, *w2h, *w2l, *whh, *whl;
    cudaGetSymbolAddress((void**)&x,   g_x);
    cudaGetSymbolAddress((void**)&qkv, g_qkv);
    cudaGetSymbolAddress((void**)&hh,  g_hh);  cudaGetSymbolAddress((void**)&hl, g_hl);
    cudaGetSymbolAddress((void**)&ah,  g_ah);  cudaGetSymbolAddress((void**)&al, g_al);
    cudaGetSymbolAddress((void**)&mh,  g_mh);  cudaGetSymbolAddress((void**)&ml, g_ml);
    cudaGetSymbolAddress((void**)&wqh, g_wqkv_h); cudaGetSymbolAddress((void**)&wql, g_wqkv_l);
    cudaGetSymbolAddress((void**)&woh, g_wo_h);   cudaGetSymbolAddress((void**)&wol, g_wo_l);
    cudaGetSymbolAddress((void**)&w1h, g_w1_h);   cudaGetSymbolAddress((void**)&w1l, g_w1_l);
    cudaGetSymbolAddress((void**)&w2h, g_w2_h);   cudaGetSymbolAddress((void**)&w2l, g_w2_l);
    cudaGetSymbolAddress((void**)&whh, g_whd_h);  cudaGetSymbolAddress((void**)&whl, g_whd_l);

    cudaFuncSetAttribute(hgemm_kernel,
                         cudaFuncAttributeMaxDynamicSharedMemorySize, HGEMM_SMEM);

    // weight conversion
    convqkv_kernel<<<(Lc * Hc * Dc * HDc + 255) / 256, 256>>>(Wq, Wk, Wv, wqh, wql);
    convw_kernel<<<dim3((Dc * Dc + 255) / 256, Lc), 256>>>(Wo, woh, wol, Dc, Dc);
    convw_kernel<<<dim3((Dc * DFFc + 255) / 256, Lc), 256>>>(W1, w1h, w1l, Dc, DFFc);
    convw_kernel<<<dim3((DFFc * Dc + 255) / 256, Lc), 256>>>(W2, w2h, w2l, DFFc, Dc);
    convw_kernel<<<dim3((Dc * Vc + 255) / 256, 1), 256>>>(Wh, whh, whl, Dc, Vc);

    // embed + ln1 of layer 0
    embed_ln_kernel<<<NTOK / 8, 256>>>(idx, tok, pos, x, hh, hl, ln1g, ln1b);

    const int MT = NTOK / 128;
    const dim3 gQKV(QKVC / 128, MT);
    const dim3 gD  (1,          MT);
    const dim3 gFF (DFFc / 128, MT);
    const dim3 gV  (Vc   / 128, MT);

    for (int l = 0; l < Lc; l++) {
        hgemm_kernel<<<gQKV, 256, HGEMM_SMEM>>>(
            hh, hl, wqh + (size_t)l * QKVC * Dc, wql + (size_t)l * QKVC * Dc,
            nullptr, nullptr, qkv, nullptr, nullptr, nullptr, nullptr,
            NTOK, QKVC, Dc, 0);
        attn_kernel<<<Bc * Hc, 256>>>(qkv, ah, al);
        hgemm_kernel<<<gD, 256, HGEMM_SMEM>>>(
            ah, al, woh + (size_t)l * Dc * Dc, wol + (size_t)l * Dc * Dc,
            bo + l * Dc, x, x, hh, hl, ln2g + l * Dc, ln2b + l * Dc,
            NTOK, Dc, Dc, 0);
        hgemm_kernel<<<gFF, 256, HGEMM_SMEM>>>(
            hh, hl, w1h + (size_t)l * DFFc * Dc, w1l + (size_t)l * DFFc * Dc,
            b1 + l * DFFc, nullptr, nullptr, mh, ml, nullptr, nullptr,
            NTOK, DFFc, Dc, 1);
        const float* ng = (l < Lc - 1) ? (ln1g + (l + 1) * Dc) : lnfg;
        const float* nb = (l < Lc - 1) ? (ln1b + (l + 1) * Dc) : lnfb;
        hgemm_kernel<<<gD, 256, HGEMM_SMEM>>>(
            mh, ml, w2h + (size_t)l * Dc * DFFc, w2l + (size_t)l * Dc * DFFc,
            b2 + l * Dc, x, x, hh, hl, ng, nb,
            NTOK, Dc, DFFc, 0);
    }

    hgemm_kernel<<<gV, 256, HGEMM_SMEM>>>(
        hh, hl, whh, whl, bhd, nullptr, out, nullptr, nullptr, nullptr, nullptr,
        NTOK, Vc, Dc, 0);
}

// round 13
// speedup vs baseline: 2.2161x; 1.6950x over previous
#include <cuda_runtime.h>
#include <cuda_fp16.h>
#include <cstdint>

// ---------------------------------------------------------------------------
// BigramTransformer forward — fp16 HMMA GEMMs (fp32 accum), double-buffered
// cp.async, fused-LN epilogues, 4-thread/row attention.
// B=2048 T=64 D=128 H=4 HD=32 L=6 V=256 DFF=512
// ---------------------------------------------------------------------------

#define Bc   2048
#define Tc   64
#define Dc   128
#define Hc   4
#define HDc  32
#define Lc   6
#define Vc   256
#define DFFc 512
#define NTOK (Bc * Tc)          /* 131072 */
#define QKVC (3 * Dc)           /* 384    */

// ------------------------- scratch (device globals) ------------------------
__device__ float g_x  [(size_t)NTOK * Dc];
__device__ float g_qkv[(size_t)NTOK * QKVC];
__device__ __half g_hh[(size_t)NTOK * Dc];
__device__ __half g_ah[(size_t)NTOK * Dc];
__device__ __half g_mh[(size_t)NTOK * DFFc];
// transposed fp16 weights [N,K]
__device__ __half g_wqkv[Lc * QKVC * Dc];
__device__ __half g_wo  [Lc * Dc * Dc];
__device__ __half g_w1  [Lc * DFFc * Dc];
__device__ __half g_w2  [Lc * Dc * DFFc];
__device__ __half g_whd [Vc * Dc];

// ------------------------- helpers ------------------------------------------
__device__ __forceinline__ uint32_t smem_u32(const void* p) {
    uint32_t a;
    asm("{ .reg .u64 t; cvta.to.shared.u64 t, %1; cvt.u32.u64 %0, t; }"
        : "=r"(a) : "l"(p));
    return a;
}
__device__ __forceinline__ void h2_store(float v0, float v1, __half* p) {
    *(__half2*)p = __floats2half2_rn(v0, v1);
}

#define LDMX4(r0, r1, r2, r3, a)                                            \
    asm volatile("ldmatrix.sync.aligned.m8n8.x4.shared.b16 {%0,%1,%2,%3}, [%4];" \
                 : "=r"(r0), "=r"(r1), "=r"(r2), "=r"(r3) : "r"(a))

#define MMA(d, a0, a1, a2, a3, b0v, b1v)                                    \
    asm volatile("mma.sync.aligned.m16n8k16.row.col.f32.f16.f16.f32 "       \
                 "{%0,%1,%2,%3}, {%4,%5,%6,%7}, {%8,%9}, {%0,%1,%2,%3};"    \
                 : "+f"((d)[0]), "+f"((d)[1]), "+f"((d)[2]), "+f"((d)[3])   \
                 : "r"(a0), "r"(a1), "r"(a2), "r"(a3), "r"(b0v), "r"(b1v))

#define CP_ASYNC16(dst, src)                                                \
    asm volatile("cp.async.cg.shared.global [%0], [%1], 16;"                \
                 :: "r"(dst), "l"(src))
#define CP_COMMIT() asm volatile("cp.async.commit_group;" ::: "memory")
#define CP_WAIT(n)  asm volatile("cp.async.wait_group %0;" :: "n"(n) : "memory")

// ------------------------- weight conversion --------------------------------
// W [K,N] f32 -> out [N,K] fp16.  blockIdx.y = layer slice.
__global__ void convw_kernel(const float* __restrict__ W,
                             __half* __restrict__ oh, int K, int N)
{
    const size_t base = (size_t)blockIdx.y * K * N;
    int i = blockIdx.x * 256 + threadIdx.x;
    if (i >= K * N) return;
    int k = i / N, n = i % N;
    oh[base + (size_t)n * K + k] = __float2half(W[base + i]);
}

// Wq/Wk/Wv [L,H,D,HD] -> wqkv_t [L, 384(N), 128(K)] fp16
__global__ void convqkv_kernel(const float* __restrict__ Wq,
                               const float* __restrict__ Wk,
                               const float* __restrict__ Wv,
                               __half* __restrict__ oh)
{
    int i = blockIdx.x * 256 + threadIdx.x;
    const int total = Lc * Hc * Dc * HDc;
    if (i >= total) return;
    int e = i % HDc;
    int d = (i / HDc) % Dc;
    int h = (i / (HDc * Dc)) % Hc;
    int l = i / (HDc * Dc * Hc);
    int src = ((l * Hc + h) * Dc + d) * HDc + e;
    const int col = h * HDc + e;
    oh[((size_t)l * QKVC + col) * Dc + d]          = __float2half(Wq[src]);
    oh[((size_t)l * QKVC + Dc + col) * Dc + d]     = __float2half(Wk[src]);
    oh[((size_t)l * QKVC + 2 * Dc + col) * Dc + d] = __float2half(Wv[src]);
}

// ------------------------- embedding + first LN (warp / token) --------------
__global__ __launch_bounds__(256) void embed_ln_kernel(
    const int* __restrict__ idx,
    const float* __restrict__ tok, const float* __restrict__ pos,
    float* __restrict__ xout, __half* __restrict__ oh,
    const float* __restrict__ gam, const float* __restrict__ bet)
{
    const int warp = threadIdx.x >> 5;
    const int lane = threadIdx.x & 31;
    const size_t n = (size_t)blockIdx.x * 8 + warp;
    const int t = (int)(n & (Tc - 1));
    const int v = idx[n];

    const float4 tv = ((const float4*)(tok + (size_t)v * Dc))[lane];
    const float4 pv = ((const float4*)(pos + (size_t)t * Dc))[lane];
    float4 x = make_float4(tv.x + pv.x, tv.y + pv.y, tv.z + pv.z, tv.w + pv.w);
    ((float4*)(xout + n * Dc))[lane] = x;

    float s = x.x + x.y + x.z + x.w;
    #pragma unroll
    for (int o = 16; o > 0; o >>= 1) s += __shfl_xor_sync(0xffffffffu, s, o);
    const float mean = s * (1.0f / Dc);

    float4 c = make_float4(x.x - mean, x.y - mean, x.z - mean, x.w - mean);
    float q = c.x * c.x + c.y * c.y + c.z * c.z + c.w * c.w;
    #pragma unroll
    for (int o = 16; o > 0; o >>= 1) q += __shfl_xor_sync(0xffffffffu, q, o);
    const float r = rsqrtf(q * (1.0f / Dc) + 1e-5f);

    const float4 g = ((const float4*)gam)[lane];
    const float4 b = ((const float4*)bet)[lane];
    h2_store(c.x * r * g.x + b.x, c.y * r * g.y + b.y, oh + n * Dc + lane * 4);
    h2_store(c.z * r * g.z + b.z, c.w * r * g.w + b.w, oh + n * Dc + lane * 4 + 2);
}

// ------------------------- fp16 HMMA GEMM (K-chunk 64, 2-stage pipeline) ----
// C[M,N] = A@B^T (+bias)(relu)(+res)
// A: [M,K] fp16 row-major; B: [N,K] fp16 row-major.
// lnG!=null (requires N==128, gridDim.x==1): write C to outf and LN(C) to outh.
#define TROWB 144                 /* 64 fp16 = 128B + 16B pad */
#define TILEB (128 * TROWB)       /* 18432B */
#define STAGEB (2 * TILEB)        /* A + B per stage */
#define HGEMM_SMEM (2 * STAGEB)   /* 73728B -> 2 CTAs/SM */

__global__ __launch_bounds__(256, 2) void hgemm_kernel(
    const __half* __restrict__ A, const __half* __restrict__ B,
    const float* __restrict__ bias, const float* __restrict__ res,
    float* __restrict__ outf, __half* __restrict__ outh,
    const float* __restrict__ lnG, const float* __restrict__ lnB,
    int M, int N, int K, int relu)
{
    extern __shared__ char smem[];
    const uint32_t sb = smem_u32(smem);

    const int tid = threadIdx.x;
    const int w   = tid >> 5;
    const int l   = tid & 31;
    const int wm  = w & 1;
    const int wn  = w >> 1;
    const int m0  = blockIdx.y * 128;
    const int n0  = blockIdx.x * 128;

    const int g    = l >> 3;
    const int idx  = l & 7;
    const int lrow = (g & 1) * 8 + idx;
    const int g2   = (g >> 1) * 16;

    const uint32_t arow = (uint32_t)(wm * 64 + lrow) * TROWB + g2;
    const uint32_t brow = (uint32_t)(wn * 32 + lrow) * TROWB + g2;

    const __half* Asrc = A + (size_t)m0 * K;
    const __half* Bsrc = B + (size_t)n0 * K;

    const int nstep = K >> 6;

    // stage chunk c into buffer (c&1)
    auto stage = [&](int c) {
        const int ck = c << 6;
        const uint32_t base = sb + (uint32_t)(c & 1) * STAGEB;
        #pragma unroll
        for (int i = tid; i < 1024; i += 256) {
            const int r  = i >> 3;
            const int c8 = i & 7;
            CP_ASYNC16(base + r * TROWB + c8 * 16,
                       Asrc + (size_t)r * K + ck + c8 * 8);
        }
        #pragma unroll
        for (int i = tid; i < 1024; i += 256) {
            const int r  = i >> 3;
            const int c8 = i & 7;
            CP_ASYNC16(base + TILEB + r * TROWB + c8 * 16,
                       Bsrc + (size_t)r * K + ck + c8 * 8);
        }
        CP_COMMIT();
    };

    float acc[4][4][4] = {};

    stage(0);
    for (int c = 0; c < nstep; c++) {
        if (c + 1 < nstep) {
            stage(c + 1);
            CP_WAIT(1);
        } else {
            CP_WAIT(0);
        }
        __syncthreads();

        const uint32_t AHo = sb + (uint32_t)(c & 1) * STAGEB;
        const uint32_t BHo = AHo + TILEB;

        #pragma unroll
        for (int ks = 0; ks < 4; ks++) {
            const uint32_t kb = ks * 32;
            uint32_t bh_[2][4];
            #pragma unroll
            for (int p = 0; p < 2; p++) {
                const uint32_t bo = brow + p * (16 * TROWB) + kb;
                LDMX4(bh_[p][0], bh_[p][1], bh_[p][2], bh_[p][3], BHo + bo);
            }
            #pragma unroll
            for (int mt = 0; mt < 4; mt++) {
                const uint32_t ao = arow + mt * (16 * TROWB) + kb;
                uint32_t a0, a1, a2, a3;
                LDMX4(a0, a1, a2, a3, AHo + ao);
                #pragma unroll
                for (int nt = 0; nt < 4; nt++) {
                    const int p = nt >> 1, q = nt & 1;
                    MMA(acc[mt][nt], a0, a1, a2, a3, bh_[p][q], bh_[p][q + 2]);
                }
            }
        }
        __syncthreads();   // protect the buffer being refilled next iteration
    }

    const int gr = l >> 2;
    const int gc = (l & 3) * 2;

    if (lnG) {
        // ---- fused epilogue: bias + residual + LN over the 128-wide row ----
        float* sums  = (float*)smem;             // [128][4]
        float* sumsq = (float*)smem + 512;       // [128][4]

        #pragma unroll
        for (int mt = 0; mt < 4; mt++) {
            #pragma unroll
            for (int h = 0; h < 2; h++) {
                const int r64 = wm * 64 + mt * 16 + gr + h * 8;
                const size_t row = (size_t)m0 + r64;
                float s = 0.f, q = 0.f;
                #pragma unroll
                for (int nt = 0; nt < 4; nt++) {
                    const int n = wn * 32 + nt * 8 + gc;
                    float v0 = acc[mt][nt][h * 2];
                    float v1 = acc[mt][nt][h * 2 + 1];
                    const float2 bb = *(const float2*)(bias + n);
                    v0 += bb.x; v1 += bb.y;
                    const float2 rr = *(const float2*)(res + row * Dc + n);
                    v0 += rr.x; v1 += rr.y;
                    acc[mt][nt][h * 2]     = v0;
                    acc[mt][nt][h * 2 + 1] = v1;
                    *(float2*)(outf + row * Dc + n) = make_float2(v0, v1);
                    s += v0 + v1;
                    q += v0 * v0 + v1 * v1;
                }
                s += __shfl_xor_sync(0xffffffffu, s, 1);
                s += __shfl_xor_sync(0xffffffffu, s, 2);
                q += __shfl_xor_sync(0xffffffffu, q, 1);
                q += __shfl_xor_sync(0xffffffffu, q, 2);
                if ((l & 3) == 0) {
                    sums [r64 * 4 + wn] = s;
                    sumsq[r64 * 4 + wn] = q;
                }
            }
        }
        __syncthreads();
        #pragma unroll
        for (int mt = 0; mt < 4; mt++) {
            #pragma unroll
            for (int h = 0; h < 2; h++) {
                const int r64 = wm * 64 + mt * 16 + gr + h * 8;
                const size_t row = (size_t)m0 + r64;
                float S = sums[r64 * 4] + sums[r64 * 4 + 1]
                        + sums[r64 * 4 + 2] + sums[r64 * 4 + 3];
                float Q = sumsq[r64 * 4] + sumsq[r64 * 4 + 1]
                        + sumsq[r64 * 4 + 2] + sumsq[r64 * 4 + 3];
                const float mean = S * (1.0f / Dc);
                const float var  = Q * (1.0f / Dc) - mean * mean;
                const float rst  = rsqrtf(var + 1e-5f);
                #pragma unroll
                for (int nt = 0; nt < 4; nt++) {
                    const int n = wn * 32 + nt * 8 + gc;
                    const float2 gg = *(const float2*)(lnG + n);
                    const float2 bb = *(const float2*)(lnB + n);
                    const float v0 = acc[mt][nt][h * 2];
                    const float v1 = acc[mt][nt][h * 2 + 1];
                    h2_store((v0 - mean) * rst * gg.x + bb.x,
                             (v1 - mean) * rst * gg.y + bb.y,
                             outh + row * Dc + n);
                }
            }
        }
        return;
    }

    // ---- plain epilogue ----
    #pragma unroll
    for (int mt = 0; mt < 4; mt++) {
        #pragma unroll
        for (int h = 0; h < 2; h++) {
            const size_t row = (size_t)m0 + wm * 64 + mt * 16 + gr + h * 8;
            #pragma unroll
            for (int nt = 0; nt < 4; nt++) {
                const int n = n0 + wn * 32 + nt * 8 + gc;
                float v0 = acc[mt][nt][h * 2];
                float v1 = acc[mt][nt][h * 2 + 1];
                if (bias) {
                    const float2 bb = *(const float2*)(bias + n);
                    v0 += bb.x; v1 += bb.y;
                }
                if (relu) { v0 = fmaxf(v0, 0.f); v1 = fmaxf(v1, 0.f); }
                if (outh) {
                    h2_store(v0, v1, outh + row * N + n);
                } else {
                    *(float2*)(outf + row * N + n) = make_float2(v0, v1);
                }
            }
        }
    }
}

// ------------------------- attention: 4 threads per row ---------------------
#define QKP 36
#define WMP 68
__global__ __launch_bounds__(256) void attn_kernel(const float* __restrict__ qkv,
                                                   __half* __restrict__ oh)
{
    __shared__ float qs[Tc][QKP];
    __shared__ float ks[Tc][QKP];
    __shared__ float vs[Tc][QKP];
    __shared__ float wm[Tc][WMP];

    const int bh  = blockIdx.x;
    const int b   = bh >> 2;
    const int h   = bh & 3;
    const int tid = threadIdx.x;

    for (int i = tid; i < 3 * Tc * 8; i += 256) {
        const int mat = i >> 9;
        const int r   = (i >> 3) & 63;
        const int j   = i & 7;
        const float4 val = *(const float4*)(qkv + ((size_t)(b * Tc + r)) * QKVC
                                            + mat * Dc + h * HDc + 4 * j);
        float* dst = (mat == 0) ? &qs[r][4 * j] : (mat == 1) ? &ks[r][4 * j]
                                                             : &vs[r][4 * j];
        *(float4*)dst = val;
    }
    __syncthreads();

    const int row = tid >> 2;
    const int sub = tid & 3;
    const float scale = 0.17677669529663687f;

    float qr[HDc];
    #pragma unroll
    for (int j = 0; j < HDc; j += 4) {
        const float4 f = *(const float4*)&qs[row][j];
        qr[j] = f.x; qr[j + 1] = f.y; qr[j + 2] = f.z; qr[j + 3] = f.w;
    }

    float wv[16];
    float mx = -1e30f;
    #pragma unroll
    for (int i = 0; i < 16; i++) {
        const int s = sub + 4 * i;
        float d = 0.f;
        #pragma unroll
        for (int j = 0; j < HDc; j += 4) {
            const float4 f = *(const float4*)&ks[s][j];
            d = fmaf(qr[j],     f.x, d);
            d = fmaf(qr[j + 1], f.y, d);
            d = fmaf(qr[j + 2], f.z, d);
            d = fmaf(qr[j + 3], f.w, d);
        }
        d *= scale;
        wv[i] = d;
        if (s <= row) mx = fmaxf(mx, d);
    }
    mx = fmaxf(mx, __shfl_xor_sync(0xffffffffu, mx, 1));
    mx = fmaxf(mx, __shfl_xor_sync(0xffffffffu, mx, 2));

    float sum = 0.f;
    #pragma unroll
    for (int i = 0; i < 16; i++) {
        const int s = sub + 4 * i;
        const float e = (s <= row) ? __expf(wv[i] - mx) : 0.f;
        wv[i] = e;
        sum += e;
    }
    sum += __shfl_xor_sync(0xffffffffu, sum, 1);
    sum += __shfl_xor_sync(0xffffffffu, sum, 2);
    const float inv = 1.f / sum;

    #pragma unroll
    for (int i = 0; i < 16; i++)
        wm[row][sub + 4 * i] = wv[i] * inv;
    __syncthreads();

    const int d0 = sub * 8;
    float acc[8] = {};
    for (int s = 0; s <= row; s++) {
        const float wgt = wm[row][s];
        const float4 v0 = *(const float4*)&vs[s][d0];
        const float4 v1 = *(const float4*)&vs[s][d0 + 4];
        acc[0] = fmaf(wgt, v0.x, acc[0]);
        acc[1] = fmaf(wgt, v0.y, acc[1]);
        acc[2] = fmaf(wgt, v0.z, acc[2]);
        acc[3] = fmaf(wgt, v0.w, acc[3]);
        acc[4] = fmaf(wgt, v1.x, acc[4]);
        acc[5] = fmaf(wgt, v1.y, acc[5]);
        acc[6] = fmaf(wgt, v1.z, acc[6]);
        acc[7] = fmaf(wgt, v1.w, acc[7]);
    }

    const size_t base = ((size_t)(b * Tc + row)) * Dc + h * HDc + d0;
    #pragma unroll
    for (int j = 0; j < 8; j += 2)
        h2_store(acc[j], acc[j + 1], oh + base + j);
}

// ------------------------- launcher -----------------------------------------
extern "C" void kernel_launch(void* const* d_in, const int* in_sizes, int n_in,
                              void* d_out, int out_size)
{
    (void)in_sizes; (void)n_in; (void)out_size;
    const int*   idx  = (const int*)  d_in[0];
    const float* tok  = (const float*)d_in[1];
    const float* pos  = (const float*)d_in[2];
    const float* Wq   = (const float*)d_in[3];
    const float* Wk   = (const float*)d_in[4];
    const float* Wv   = (const float*)d_in[5];
    const float* Wo   = (const float*)d_in[6];
    const float* bo   = (const float*)d_in[7];
    const float* ln1g = (const float*)d_in[8];
    const float* ln1b = (const float*)d_in[9];
    const float* W1   = (const float*)d_in[10];
    const float* b1   = (const float*)d_in[11];
    const float* W2   = (const float*)d_in[12];
    const float* b2   = (const float*)d_in[13];
    const float* ln2g = (const float*)d_in[14];
    const float* ln2b = (const float*)d_in[15];
    const float* lnfg = (const float*)d_in[16];
    const float* lnfb = (const float*)d_in[17];
    const float* Wh   = (const float*)d_in[18];
    const float* bhd  = (const float*)d_in[19];
    float* out = (float*)d_out;

    float *x, *qkv;
    __half *hh, *ah, *mh, *wq, *wo, *w1, *w2, *whd;
    cudaGetSymbolAddress((void**)&x,   g_x);
    cudaGetSymbolAddress((void**)&qkv, g_qkv);
    cudaGetSymbolAddress((void**)&hh,  g_hh);
    cudaGetSymbolAddress((void**)&ah,  g_ah);
    cudaGetSymbolAddress((void**)&mh,  g_mh);
    cudaGetSymbolAddress((void**)&wq,  g_wqkv);
    cudaGetSymbolAddress((void**)&wo,  g_wo);
    cudaGetSymbolAddress((void**)&w1,  g_w1);
    cudaGetSymbolAddress((void**)&w2,  g_w2);
    cudaGetSymbolAddress((void**)&whd, g_whd);

    cudaFuncSetAttribute(hgemm_kernel,
                         cudaFuncAttributeMaxDynamicSharedMemorySize, HGEMM_SMEM);

    // weight conversion
    convqkv_kernel<<<(Lc * Hc * Dc * HDc + 255) / 256, 256>>>(Wq, Wk, Wv, wq);
    convw_kernel<<<dim3((Dc * Dc + 255) / 256, Lc), 256>>>(Wo, wo, Dc, Dc);
    convw_kernel<<<dim3((Dc * DFFc + 255) / 256, Lc), 256>>>(W1, w1, Dc, DFFc);
    convw_kernel<<<dim3((DFFc * Dc + 255) / 256, Lc), 256>>>(W2, w2, DFFc, Dc);
    convw_kernel<<<dim3((Dc * Vc + 255) / 256, 1), 256>>>(Wh, whd, Dc, Vc);

    // embed + ln1 of layer 0
    embed_ln_kernel<<<NTOK / 8, 256>>>(idx, tok, pos, x, hh, ln1g, ln1b);

    const int MT = NTOK / 128;
    const dim3 gQKV(QKVC / 128, MT);
    const dim3 gD  (1,          MT);
    const dim3 gFF (DFFc / 128, MT);
    const dim3 gV  (Vc   / 128, MT);

    for (int l = 0; l < Lc; l++) {
        hgemm_kernel<<<gQKV, 256, HGEMM_SMEM>>>(
            hh, wq + (size_t)l * QKVC * Dc,
            nullptr, nullptr, qkv, nullptr, nullptr, nullptr,
            NTOK, QKVC, Dc, 0);
        attn_kernel<<<Bc * Hc, 256>>>(qkv, ah);
        hgemm_kernel<<<gD, 256, HGEMM_SMEM>>>(
            ah, wo + (size_t)l * Dc * Dc,
            bo + l * Dc, x, x, hh, ln2g + l * Dc, ln2b + l * Dc,
            NTOK, Dc, Dc, 0);
        hgemm_kernel<<<gFF, 256, HGEMM_SMEM>>>(
            hh, w1 + (size_t)l * DFFc * Dc,
            b1 + l * DFFc, nullptr, nullptr, mh, nullptr, nullptr,
            NTOK, DFFc, Dc, 1);
        const float* ng = (l < Lc - 1) ? (ln1g + (l + 1) * Dc) : lnfg;
        const float* nb = (l < Lc - 1) ? (ln1b + (l + 1) * Dc) : lnfb;
        hgemm_kernel<<<gD, 256, HGEMM_SMEM>>>(
            mh, w2 + (size_t)l * Dc * DFFc,
            b2 + l * Dc, x, x, hh, ng, nb,
            NTOK, Dc, DFFc, 0);
    }

    hgemm_kernel<<<gV, 256, HGEMM_SMEM>>>(
        hh, whd, bhd, nullptr, out, nullptr, nullptr, nullptr,
        NTOK, Vc, Dc, 0);
}